// round 9
// baseline (speedup 1.0000x reference)
#include <cuda_runtime.h>
#include <cuda_fp16.h>
#include <math.h>
#include <stdint.h>

// ---------------- problem constants ----------------
#define T_SEQ   2048
#define HID     2048
#define NUM_K   16
#define NUM_V   32
#define DK      128
#define DV      128
#define KEY_DIM 2048
#define VAL_DIM 4096
#define CONV_DIM 8192
#define QKVZ_N  12288
#define QSCALE  0.08838834764831845f

// ---------------- scratch ----------------
__device__ float  g_qkvz  [T_SEQ * QKVZ_N];
__device__ float  g_qkv   [T_SEQ * CONV_DIM];
__device__ float  g_ba    [T_SEQ * 64];
__device__ float2 g_egbeta[T_SEQ * NUM_V];
__device__ float  g_qhat  [T_SEQ * KEY_DIM];
__device__ float  g_khat  [T_SEQ * KEY_DIM];
__device__ float  g_qkdot [T_SEQ * NUM_K];
__device__ float  g_oscan [T_SEQ * VAL_DIM];

// fp16 operands: weights single fp16 (W^T), activations split hi/lo
__device__ __half g_Wq[QKVZ_N * HID];
__device__ __half g_Wo[HID * VAL_DIM];
__device__ __half g_A_hi[T_SEQ * VAL_DIM];
__device__ __half g_A_lo[T_SEQ * VAL_DIM];

// ---------------- helpers ----------------
__device__ __forceinline__ float sigmoidf_(float x) { return 1.0f / (1.0f + __expf(-x)); }
__device__ __forceinline__ float siluf_(float x)    { return x * sigmoidf_(x); }

__device__ __forceinline__ uint32_t smem_to_u32(const void* p) {
    uint32_t a;
    asm("{ .reg .u64 t; cvta.to.shared.u64 t, %1; cvt.u32.u64 %0, t; }" : "=r"(a) : "l"(p));
    return a;
}
__device__ __forceinline__ void ldsm4(uint32_t& r0, uint32_t& r1, uint32_t& r2, uint32_t& r3,
                                      uint32_t addr) {
    asm volatile("ldmatrix.sync.aligned.m8n8.x4.shared.b16 {%0,%1,%2,%3}, [%4];"
                 : "=r"(r0), "=r"(r1), "=r"(r2), "=r"(r3) : "r"(addr));
}
__device__ __forceinline__ void mma16816(float* d, const uint32_t* a, const uint32_t* b) {
    asm volatile("mma.sync.aligned.m16n8k16.row.col.f32.f16.f16.f32 "
                 "{%0,%1,%2,%3}, {%4,%5,%6,%7}, {%8,%9}, {%0,%1,%2,%3};"
                 : "+f"(d[0]), "+f"(d[1]), "+f"(d[2]), "+f"(d[3])
                 : "r"(a[0]), "r"(a[1]), "r"(a[2]), "r"(a[3]), "r"(b[0]), "r"(b[1]));
}

// ---------------- prep: fp32 -> fp16 hi/lo split ----------------
__global__ __launch_bounds__(256) void cvt_split(
    const float* __restrict__ x, __half* __restrict__ hi,
    __half* __restrict__ lo, int n4)
{
    int i = blockIdx.x * 256 + threadIdx.x;
    if (i >= n4) return;
    float4 v = ((const float4*)x)[i];
    __half h0 = __float2half_rn(v.x), h1 = __float2half_rn(v.y);
    __half h2 = __float2half_rn(v.z), h3 = __float2half_rn(v.w);
    __half l0 = __float2half_rn(v.x - __half2float(h0));
    __half l1 = __float2half_rn(v.y - __half2float(h1));
    __half l2 = __float2half_rn(v.z - __half2float(h2));
    __half l3 = __float2half_rn(v.w - __half2float(h3));
    union { __half2 h2v[2]; uint2 u; } H, L;
    H.h2v[0] = __halves2half2(h0, h1); H.h2v[1] = __halves2half2(h2, h3);
    L.h2v[0] = __halves2half2(l0, l1); L.h2v[1] = __halves2half2(l2, l3);
    ((uint2*)hi)[i] = H.u;
    ((uint2*)lo)[i] = L.u;
}

// ---------------- prep: W [K][N] fp32 -> W^T [N][K] fp16 ----------------
__global__ __launch_bounds__(256) void tr_half(
    const float* __restrict__ W, __half* __restrict__ out, int K, int N)
{
    __shared__ float t[32][33];
    int n0 = blockIdx.x * 32, k0 = blockIdx.y * 32;
    int tx = threadIdx.x, ty = threadIdx.y;
#pragma unroll
    for (int j = 0; j < 4; ++j)
        t[ty + j * 8][tx] = W[(size_t)(k0 + ty + j * 8) * N + n0 + tx];
    __syncthreads();
#pragma unroll
    for (int j = 0; j < 4; ++j) {
        int n = ty + j * 8;
        out[(size_t)(n0 + n) * K + k0 + tx] = __float2half_rn(t[tx][n]);
    }
}

// ---------------- mma.sync GEMM: 128x256 CTA, 64x64 warp tiles, cp.async 5-stage ----------------
#define SSTR   80
#define SZ_A   (128 * SSTR)
#define SZ_B   (256 * SSTR)
#define BUF_SZ (2 * SZ_A + SZ_B)        // 40960
#define NSTAGE 5
#define GT_SMEM (NSTAGE * BUF_SZ)       // 204800

template<int ITERS>
__device__ __forceinline__ void cpa_stage(uint32_t sdst, const char* g, int Kb, int tid) {
#pragma unroll
    for (int i = 0; i < ITERS; ++i) {
        int idx = tid + i * 256;
        int row = idx >> 2;
        int q   = (idx & 3) << 4;
        uint32_t d = sdst + row * SSTR + q;
        const char* s = g + (size_t)row * Kb + q;
        asm volatile("cp.async.cg.shared.global [%0], [%1], 16;" :: "r"(d), "l"(s));
    }
}

__global__ __launch_bounds__(256, 1) void gemm_tc(
    const __half* __restrict__ Ahi, const __half* __restrict__ Alo,
    const __half* __restrict__ B, float* __restrict__ C, int N, int K)
{
    extern __shared__ __align__(128) char smem[];
    const uint32_t sb = smem_to_u32(smem);

    const int tid  = threadIdx.x;
    const int wid  = tid >> 5;
    const int lane = tid & 31;
    const int bm   = blockIdx.x * 128;
    const int bn   = blockIdx.y * 256;
    const int wm   = (wid >> 2) * 64;
    const int wn   = (wid & 3) * 64;
    const int Kb   = K * 2;

    const char* gAh = (const char*)(Ahi + (size_t)bm * K);
    const char* gAl = (const char*)(Alo + (size_t)bm * K);
    const char* gB  = (const char*)(B   + (size_t)bn * K);

    float acc[4][8][4];
#pragma unroll
    for (int i = 0; i < 4; ++i)
#pragma unroll
        for (int j = 0; j < 8; ++j)
#pragma unroll
            for (int r = 0; r < 4; ++r) acc[i][j][r] = 0.0f;

    const uint32_t aoff = (lane & 15) * SSTR + ((lane >> 4) << 4);
    const uint32_t boff = ((lane & 7) + ((lane >> 4) << 3)) * SSTR + (((lane >> 3) & 1) << 4);

    const int nk = K >> 5;

    // prologue: stage chunks 0..3
#pragma unroll
    for (int p = 0; p < 4; ++p) {
        uint32_t sbuf = sb + p * BUF_SZ;
        size_t ko = (size_t)p * 64;
        cpa_stage<2>(sbuf,            gAh + ko, Kb, tid);
        cpa_stage<2>(sbuf + SZ_A,     gAl + ko, Kb, tid);
        cpa_stage<4>(sbuf + 2 * SZ_A, gB  + ko, Kb, tid);
        asm volatile("cp.async.commit_group;");
    }

    int buf = 0;       // buffer of chunk kt
    int nbuf = 4;      // buffer for chunk kt+4
    for (int kt = 0; kt < nk; ++kt) {
        asm volatile("cp.async.wait_group 3;");
        __syncthreads();

        if (kt + 4 < nk) {
            uint32_t sbuf = sb + nbuf * BUF_SZ;
            size_t ko = (size_t)(kt + 4) * 64;
            cpa_stage<2>(sbuf,            gAh + ko, Kb, tid);
            cpa_stage<2>(sbuf + SZ_A,     gAl + ko, Kb, tid);
            cpa_stage<4>(sbuf + 2 * SZ_A, gB  + ko, Kb, tid);
        }
        asm volatile("cp.async.commit_group;");

        const uint32_t sAh = sb + buf * BUF_SZ;
        const uint32_t sAl = sAh + SZ_A;
        const uint32_t sB  = sAh + 2 * SZ_A;

#pragma unroll
        for (int ks = 0; ks < 2; ++ks) {
            const uint32_t kb = ks * 32;
            uint32_t ah[4][4], al[4][4];
#pragma unroll
            for (int mt = 0; mt < 4; ++mt) {
                uint32_t base = (wm + mt * 16) * SSTR + aoff + kb;
                ldsm4(ah[mt][0], ah[mt][1], ah[mt][2], ah[mt][3], sAh + base);
                ldsm4(al[mt][0], al[mt][1], al[mt][2], al[mt][3], sAl + base);
            }
#pragma unroll
            for (int pr = 0; pr < 4; ++pr) {
                uint32_t bbase = (wn + pr * 16) * SSTR + boff + kb;
                uint32_t h0, h1, h2, h3;
                ldsm4(h0, h1, h2, h3, sB + bbase);
                uint32_t b0[2] = {h0, h1}, b1[2] = {h2, h3};
#pragma unroll
                for (int mt = 0; mt < 4; ++mt) {
                    mma16816(acc[mt][2 * pr],     ah[mt], b0);
                    mma16816(acc[mt][2 * pr + 1], ah[mt], b1);
                    mma16816(acc[mt][2 * pr],     al[mt], b0);
                    mma16816(acc[mt][2 * pr + 1], al[mt], b1);
                }
            }
        }
        buf  = (buf  + 1 == NSTAGE) ? 0 : buf  + 1;
        nbuf = (nbuf + 1 == NSTAGE) ? 0 : nbuf + 1;
    }

    const int g  = lane >> 2;
    const int tg = lane & 3;
#pragma unroll
    for (int mt = 0; mt < 4; ++mt) {
#pragma unroll
        for (int nt = 0; nt < 8; ++nt) {
            const float* d = acc[mt][nt];
            size_t r = (size_t)(bm + wm + mt * 16 + g) * N + bn + wn + nt * 8 + tg * 2;
            *(float2*)&C[r] = make_float2(d[0], d[1]);
            *(float2*)&C[r + 8 * (size_t)N] = make_float2(d[2], d[3]);
        }
    }
}

// ---------------- tiled small GEMM: ba = h @ W_ba (2048x64, K=2048) ----------------
__global__ __launch_bounds__(256) void gemm_ba(
    const float* __restrict__ A, const float* __restrict__ B, float* __restrict__ C)
{
    __shared__ float sh[64][65];
    __shared__ float sB[64][65];
    const int tid = threadIdx.x;
    const int col = tid & 63;
    const int rg  = tid >> 6;
    const int br  = blockIdx.x * 64;

    float acc[16];
#pragma unroll
    for (int r = 0; r < 16; ++r) acc[r] = 0.0f;

    for (int kt = 0; kt < HID / 64; ++kt) {
#pragma unroll
        for (int i = 0; i < 16; ++i) {
            int idx = tid + i * 256;
            int row = idx >> 6, kk = idx & 63;
            sh[row][kk] = A[(size_t)(br + row) * HID + kt * 64 + kk];
            sB[row][kk] = B[(size_t)(kt * 64 + row) * 64 + kk];
        }
        __syncthreads();
#pragma unroll 16
        for (int kk = 0; kk < 64; ++kk) {
            float b = sB[kk][col];
#pragma unroll
            for (int r = 0; r < 16; ++r)
                acc[r] = fmaf(sh[rg * 16 + r][kk], b, acc[r]);
        }
        __syncthreads();
    }
#pragma unroll
    for (int r = 0; r < 16; ++r)
        C[(size_t)(br + rg * 16 + r) * 64 + col] = acc[r];
}

// ---------------- causal depthwise conv (K=4) + SiLU, 4 t per thread ----------------
__global__ __launch_bounds__(256) void conv_silu(
    const float* __restrict__ qkvz, const float* __restrict__ conv_w,
    float* __restrict__ out)
{
    int idx = blockIdx.x * blockDim.x + threadIdx.x;
    if (idx >= (T_SEQ / 4) * CONV_DIM) return;
    int tq = idx >> 13;
    int c  = idx & (CONV_DIM - 1);
    int t0 = tq * 4;
    const float* w = conv_w + c * 4;
    float xv[7];
#pragma unroll
    for (int j = 0; j < 7; ++j) {
        int tt = t0 - 3 + j;
        xv[j] = (tt >= 0) ? qkvz[(size_t)tt * QKVZ_N + c] : 0.0f;
    }
#pragma unroll
    for (int i = 0; i < 4; ++i) {
        float a = w[0] * xv[i];
        a = fmaf(w[1], xv[i + 1], a);
        a = fmaf(w[2], xv[i + 2], a);
        a = fmaf(w[3], xv[i + 3], a);
        out[(size_t)(t0 + i) * CONV_DIM + c] = siluf_(a);
    }
}

// ---------------- gating ----------------
__global__ __launch_bounds__(256) void gate_prep(
    const float* __restrict__ ba, const float* __restrict__ A_log,
    const float* __restrict__ dt_bias, float2* __restrict__ egbeta)
{
    int i = blockIdx.x * blockDim.x + threadIdx.x;
    if (i >= T_SEQ * NUM_V) return;
    int t = i >> 5;
    int h = i & 31;
    float b = ba[(size_t)t * 64 + h];
    float a = ba[(size_t)t * 64 + 32 + h];
    float x = a + dt_bias[h];
    float sp = (x > 20.0f) ? x : log1pf(expf(x));
    float g = -expf(A_log[h]) * sp;
    egbeta[i] = make_float2(expf(g), sigmoidf_(b));
}

// ---------------- fused l2norm(q,k) + qk dot: one warp per (t, key-head) ----------------
__global__ __launch_bounds__(256) void l2norm_qk_dot(
    const float* __restrict__ qkv, float* __restrict__ qhat,
    float* __restrict__ khat, float* __restrict__ qkdot)
{
    int gid  = blockIdx.x * 8 + (threadIdx.x >> 5);   // over T_SEQ*NUM_K
    int lane = threadIdx.x & 31;
    int t  = gid >> 4;
    int kh = gid & 15;
    const float* qsrc = qkv + (size_t)t * CONV_DIM + kh * DK;
    float4 q = *((const float4*)qsrc + lane);
    float4 k = *((const float4*)(qsrc + KEY_DIM) + lane);
    float sq  = q.x * q.x + q.y * q.y + q.z * q.z + q.w * q.w;
    float sk  = k.x * k.x + k.y * k.y + k.z * k.z + k.w * k.w;
    float sqk = q.x * k.x + q.y * k.y + q.z * k.z + q.w * k.w;
#pragma unroll
    for (int off = 16; off > 0; off >>= 1) {
        sq  += __shfl_xor_sync(0xffffffffu, sq,  off);
        sk  += __shfl_xor_sync(0xffffffffu, sk,  off);
        sqk += __shfl_xor_sync(0xffffffffu, sqk, off);
    }
    float rq = rsqrtf(sq + 1e-6f) * QSCALE;
    float rk = rsqrtf(sk + 1e-6f);
    size_t base = (size_t)t * KEY_DIM + kh * DK;
    *((float4*)(qhat + base) + lane) = make_float4(q.x * rq, q.y * rq, q.z * rq, q.w * rq);
    *((float4*)(khat + base) + lane) = make_float4(k.x * rk, k.y * rk, k.z * rk, k.w * rk);
    if (lane == 0) qkdot[t * NUM_K + kh] = sqk * rq * rk;
}

// ---------------- gated delta scan: one warp per (head, v-column), prefetch depth 2 ----------------
__global__ __launch_bounds__(256) void gdn_scan(
    const float* __restrict__ qhat, const float* __restrict__ khat,
    const float* __restrict__ qkv, const float2* __restrict__ egbeta,
    const float* __restrict__ qk, float* __restrict__ o)
{
    const int warp = threadIdx.x >> 5;
    const int lane = threadIdx.x & 31;
    const int h   = blockIdx.x >> 4;
    const int col = ((blockIdx.x & 15) << 3) + warp;
    const int kh  = h >> 1;

    const float4* kp = (const float4*)(khat + kh * DK) + lane;
    const float4* qp = (const float4*)(qhat + kh * DK) + lane;
    const float*  vp = qkv + 2 * KEY_DIM + h * DV + col;
    const float2* ep = egbeta + h;
    const float*  xp = qk + kh;
    float*        op = o + h * DV + col;

    const int SK = KEY_DIM / 4;

    float S0 = 0.f, S1 = 0.f, S2 = 0.f, S3 = 0.f;

    // prefetch queue: A = t, B = t+1
    float4 kkA = kp[0], qqA = qp[0];
    float  vtA = vp[0], xqA = xp[0];
    float2 ebA = ep[0];
    float4 kkB = kp[SK], qqB = qp[SK];
    float  vtB = vp[CONV_DIM], xqB = xp[NUM_K];
    float2 ebB = ep[NUM_V];

    for (int t = 0; t < T_SEQ; ++t) {
        // prefetch t+2
        float4 kkC, qqC; float vtC, xqC; float2 ebC;
        if (t + 2 < T_SEQ) {
            size_t s2 = (size_t)(t + 2);
            kkC = kp[s2 * SK];
            qqC = qp[s2 * SK];
            vtC = vp[s2 * CONV_DIM];
            ebC = ep[s2 * NUM_V];
            xqC = xp[s2 * NUM_K];
        } else {
            kkC = kkB; qqC = qqB; vtC = vtB; ebC = ebB; xqC = xqB;
        }

        float dk = kkA.x * S0 + kkA.y * S1 + kkA.z * S2 + kkA.w * S3;
        float dq = qqA.x * S0 + qqA.y * S1 + qqA.z * S2 + qqA.w * S3;
#pragma unroll
        for (int off = 16; off > 0; off >>= 1) {
            dk += __shfl_xor_sync(0xffffffffu, dk, off);
            dq += __shfl_xor_sync(0xffffffffu, dq, off);
        }
        const float eg = ebA.x, beta = ebA.y;
        const float delta = (vtA - eg * dk) * beta;
        const float ot    = fmaf(eg, dq, xqA * delta);
        S0 = fmaf(S0, eg, kkA.x * delta);
        S1 = fmaf(S1, eg, kkA.y * delta);
        S2 = fmaf(S2, eg, kkA.z * delta);
        S3 = fmaf(S3, eg, kkA.w * delta);
        if (lane == 0) *op = ot;
        op += VAL_DIM;

        kkA = kkB; qqA = qqB; vtA = vtB; ebA = ebB; xqA = xqB;
        kkB = kkC; qqB = qqC; vtB = vtC; ebB = ebC; xqB = xqC;
    }
}

// ---------------- RMSNorm * norm_w * silu(z), write fp16 hi/lo directly ----------------
__global__ __launch_bounds__(256) void rms_gate_split(
    const float* __restrict__ o, const float* __restrict__ qkvz,
    const float* __restrict__ norm_w,
    __half* __restrict__ hi, __half* __restrict__ lo)
{
    int gid  = blockIdx.x * 8 + (threadIdx.x >> 5);
    int lane = threadIdx.x & 31;
    int t = gid >> 5;
    int h = gid & 31;
    const float* orow = o + (size_t)t * VAL_DIM + h * DV;
    float4 x = *(const float4*)(orow + lane * 4);
    float s = x.x * x.x + x.y * x.y + x.z * x.z + x.w * x.w;
#pragma unroll
    for (int off = 16; off > 0; off >>= 1) s += __shfl_xor_sync(0xffffffffu, s, off);
    float r = rsqrtf(s * (1.0f / DV) + 1e-6f);
    float4 z  = *(const float4*)(qkvz + (size_t)t * QKVZ_N + 2 * KEY_DIM + VAL_DIM + h * DV + lane * 4);
    float4 nw = *(const float4*)(norm_w + lane * 4);
    float4 y;
    y.x = x.x * r * nw.x * siluf_(z.x);
    y.y = x.y * r * nw.y * siluf_(z.y);
    y.z = x.z * r * nw.z * siluf_(z.z);
    y.w = x.w * r * nw.w * siluf_(z.w);
    __half h0 = __float2half_rn(y.x), h1 = __float2half_rn(y.y);
    __half h2 = __float2half_rn(y.z), h3 = __float2half_rn(y.w);
    __half l0 = __float2half_rn(y.x - __half2float(h0));
    __half l1 = __float2half_rn(y.y - __half2float(h1));
    __half l2 = __float2half_rn(y.z - __half2float(h2));
    __half l3 = __float2half_rn(y.w - __half2float(h3));
    union { __half2 h2v[2]; uint2 u; } H, L;
    H.h2v[0] = __halves2half2(h0, h1); H.h2v[1] = __halves2half2(h2, h3);
    L.h2v[0] = __halves2half2(l0, l1); L.h2v[1] = __halves2half2(l2, l3);
    int i4 = (t * VAL_DIM + h * DV) / 4 + lane;
    ((uint2*)hi)[i4] = H.u;
    ((uint2*)lo)[i4] = L.u;
}

// ---------------- launch ----------------
extern "C" void kernel_launch(void* const* d_in, const int* in_sizes, int n_in,
                              void* d_out, int out_size)
{
    const float* h_in    = (const float*)d_in[0];
    const float* W_qkvz  = (const float*)d_in[1];
    const float* W_ba    = (const float*)d_in[2];
    const float* conv_w  = (const float*)d_in[3];
    const float* dt_bias = (const float*)d_in[4];
    const float* A_log   = (const float*)d_in[5];
    const float* norm_w  = (const float*)d_in[6];
    const float* W_out   = (const float*)d_in[7];
    float* out = (float*)d_out;

    float *qkvz, *qkv, *ba, *qhat, *khat, *qkdot, *oscan;
    float2* egbeta;
    __half *Wq, *Wo, *A_hi, *A_lo;
    cudaGetSymbolAddress((void**)&qkvz,   g_qkvz);
    cudaGetSymbolAddress((void**)&qkv,    g_qkv);
    cudaGetSymbolAddress((void**)&ba,     g_ba);
    cudaGetSymbolAddress((void**)&egbeta, g_egbeta);
    cudaGetSymbolAddress((void**)&qhat,   g_qhat);
    cudaGetSymbolAddress((void**)&khat,   g_khat);
    cudaGetSymbolAddress((void**)&qkdot,  g_qkdot);
    cudaGetSymbolAddress((void**)&oscan,  g_oscan);
    cudaGetSymbolAddress((void**)&Wq,     g_Wq);
    cudaGetSymbolAddress((void**)&Wo,     g_Wo);
    cudaGetSymbolAddress((void**)&A_hi,   g_A_hi);
    cudaGetSymbolAddress((void**)&A_lo,   g_A_lo);

    cudaFuncSetAttribute(gemm_tc, cudaFuncAttributeMaxDynamicSharedMemorySize, GT_SMEM);

    // prep
    {
        dim3 blk(32, 8);
        tr_half<<<dim3(QKVZ_N / 32, HID / 32), blk>>>(W_qkvz, Wq, HID, QKVZ_N);
        tr_half<<<dim3(HID / 32, VAL_DIM / 32), blk>>>(W_out, Wo, VAL_DIM, HID);
    }
    cvt_split<<<(T_SEQ * HID / 4 + 255) / 256, 256>>>(h_in, A_hi, A_lo, T_SEQ * HID / 4);

    // GEMM1: qkvz = h @ W_qkvz   [2048 x 12288], K=2048
    gemm_tc<<<dim3(T_SEQ / 128, QKVZ_N / 256), 256, GT_SMEM>>>(A_hi, A_lo, Wq, qkvz, QKVZ_N, HID);

    gemm_ba<<<T_SEQ / 64, 256>>>(h_in, W_ba, ba);
    conv_silu<<<((T_SEQ / 4) * CONV_DIM) / 256, 256>>>(qkvz, conv_w, qkv);
    gate_prep<<<(T_SEQ * NUM_V) / 256, 256>>>(ba, A_log, dt_bias, egbeta);
    l2norm_qk_dot<<<(T_SEQ * NUM_K) / 8, 256>>>(qkv, qhat, khat, qkdot);
    gdn_scan<<<NUM_V * 16, 256>>>(qhat, khat, qkv, egbeta, qkdot, oscan);
    rms_gate_split<<<(T_SEQ * NUM_V) / 8, 256>>>(oscan, qkvz, norm_w, A_hi, A_lo);

    // GEMM2: out = gated @ W_out  [2048 x 2048], K=4096
    gemm_tc<<<dim3(T_SEQ / 128, HID / 256), 256, GT_SMEM>>>(A_hi, A_lo, Wo, out, HID, VAL_DIM);
}

// round 10
// speedup vs baseline: 1.0445x; 1.0445x over previous
#include <cuda_runtime.h>
#include <cuda_fp16.h>
#include <math.h>
#include <stdint.h>

// ---------------- problem constants ----------------
#define T_SEQ   2048
#define HID     2048
#define NUM_K   16
#define NUM_V   32
#define DK      128
#define DV      128
#define KEY_DIM 2048
#define VAL_DIM 4096
#define CONV_DIM 8192
#define QKVZ_N  12288
#define QSCALE  0.08838834764831845f

// ---------------- scratch ----------------
__device__ float  g_qkvz  [T_SEQ * QKVZ_N];
__device__ float  g_qkv   [T_SEQ * CONV_DIM];
__device__ float  g_ba    [T_SEQ * 64];
__device__ float2 g_egbeta[T_SEQ * NUM_V];
__device__ float  g_qhat  [T_SEQ * KEY_DIM];
__device__ float  g_khat  [T_SEQ * KEY_DIM];
__device__ float  g_qkdot [T_SEQ * NUM_K];
__device__ float  g_oscan [T_SEQ * VAL_DIM];

// fp16 operands: weights single fp16 (W^T), activations split hi/lo
__device__ __half g_Wq[QKVZ_N * HID];
__device__ __half g_Wo[HID * VAL_DIM];
__device__ __half g_A_hi[T_SEQ * VAL_DIM];
__device__ __half g_A_lo[T_SEQ * VAL_DIM];

// ---------------- helpers ----------------
__device__ __forceinline__ float sigmoidf_(float x) { return 1.0f / (1.0f + __expf(-x)); }
__device__ __forceinline__ float siluf_(float x)    { return x * sigmoidf_(x); }

__device__ __forceinline__ uint32_t smem_to_u32(const void* p) {
    uint32_t a;
    asm("{ .reg .u64 t; cvta.to.shared.u64 t, %1; cvt.u32.u64 %0, t; }" : "=r"(a) : "l"(p));
    return a;
}
__device__ __forceinline__ void ldsm4(uint32_t& r0, uint32_t& r1, uint32_t& r2, uint32_t& r3,
                                      uint32_t addr) {
    asm volatile("ldmatrix.sync.aligned.m8n8.x4.shared.b16 {%0,%1,%2,%3}, [%4];"
                 : "=r"(r0), "=r"(r1), "=r"(r2), "=r"(r3) : "r"(addr));
}
__device__ __forceinline__ void mma16816(float* d, const uint32_t* a, const uint32_t* b) {
    asm volatile("mma.sync.aligned.m16n8k16.row.col.f32.f16.f16.f32 "
                 "{%0,%1,%2,%3}, {%4,%5,%6,%7}, {%8,%9}, {%0,%1,%2,%3};"
                 : "+f"(d[0]), "+f"(d[1]), "+f"(d[2]), "+f"(d[3])
                 : "r"(a[0]), "r"(a[1]), "r"(a[2]), "r"(a[3]), "r"(b[0]), "r"(b[1]));
}

// ---------------- prep: fp32 -> fp16 hi/lo split ----------------
__global__ __launch_bounds__(256) void cvt_split(
    const float* __restrict__ x, __half* __restrict__ hi,
    __half* __restrict__ lo, int n4)
{
    int i = blockIdx.x * 256 + threadIdx.x;
    if (i >= n4) return;
    float4 v = ((const float4*)x)[i];
    __half h0 = __float2half_rn(v.x), h1 = __float2half_rn(v.y);
    __half h2 = __float2half_rn(v.z), h3 = __float2half_rn(v.w);
    __half l0 = __float2half_rn(v.x - __half2float(h0));
    __half l1 = __float2half_rn(v.y - __half2float(h1));
    __half l2 = __float2half_rn(v.z - __half2float(h2));
    __half l3 = __float2half_rn(v.w - __half2float(h3));
    union { __half2 h2v[2]; uint2 u; } H, L;
    H.h2v[0] = __halves2half2(h0, h1); H.h2v[1] = __halves2half2(h2, h3);
    L.h2v[0] = __halves2half2(l0, l1); L.h2v[1] = __halves2half2(l2, l3);
    ((uint2*)hi)[i] = H.u;
    ((uint2*)lo)[i] = L.u;
}

// ---------------- prep: W [K][N] fp32 -> W^T [N][K] fp16 ----------------
__global__ __launch_bounds__(256) void tr_half(
    const float* __restrict__ W, __half* __restrict__ out, int K, int N)
{
    __shared__ float t[32][33];
    int n0 = blockIdx.x * 32, k0 = blockIdx.y * 32;
    int tx = threadIdx.x, ty = threadIdx.y;
#pragma unroll
    for (int j = 0; j < 4; ++j)
        t[ty + j * 8][tx] = W[(size_t)(k0 + ty + j * 8) * N + n0 + tx];
    __syncthreads();
#pragma unroll
    for (int j = 0; j < 4; ++j) {
        int n = ty + j * 8;
        out[(size_t)(n0 + n) * K + k0 + tx] = __float2half_rn(t[tx][n]);
    }
}

// ---------------- mma.sync GEMM: 128x256 CTA, 512 threads, 16 warps (4x4), 32x64 warp tiles ----------------
#define SSTR   80
#define SZ_A   (128 * SSTR)
#define SZ_B   (256 * SSTR)
#define BUF_SZ (2 * SZ_A + SZ_B)        // 40960
#define NSTAGE 3
#define GT_SMEM (NSTAGE * BUF_SZ)       // 122880

template<int ITERS>
__device__ __forceinline__ void cpa_stage(uint32_t sdst, const char* g, int Kb, int tid) {
#pragma unroll
    for (int i = 0; i < ITERS; ++i) {
        int idx = tid + i * 512;
        int row = idx >> 2;
        int q   = (idx & 3) << 4;
        uint32_t d = sdst + row * SSTR + q;
        const char* s = g + (size_t)row * Kb + q;
        asm volatile("cp.async.cg.shared.global [%0], [%1], 16;" :: "r"(d), "l"(s));
    }
}

__global__ __launch_bounds__(512, 1) void gemm_tc(
    const __half* __restrict__ Ahi, const __half* __restrict__ Alo,
    const __half* __restrict__ B, float* __restrict__ C, int N, int K)
{
    extern __shared__ __align__(128) char smem[];
    const uint32_t sb = smem_to_u32(smem);

    const int tid  = threadIdx.x;
    const int wid  = tid >> 5;
    const int lane = tid & 31;
    const int bm   = blockIdx.x * 128;
    const int bn   = blockIdx.y * 256;
    const int wm   = (wid >> 2) * 32;    // 4 warp-rows of 32
    const int wn   = (wid & 3) * 64;     // 4 warp-cols of 64
    const int Kb   = K * 2;

    const char* gAh = (const char*)(Ahi + (size_t)bm * K);
    const char* gAl = (const char*)(Alo + (size_t)bm * K);
    const char* gB  = (const char*)(B   + (size_t)bn * K);

    float acc[2][8][4];
#pragma unroll
    for (int i = 0; i < 2; ++i)
#pragma unroll
        for (int j = 0; j < 8; ++j)
#pragma unroll
            for (int r = 0; r < 4; ++r) acc[i][j][r] = 0.0f;

    const uint32_t aoff = (lane & 15) * SSTR + ((lane >> 4) << 4);
    const uint32_t boff = ((lane & 7) + ((lane >> 4) << 3)) * SSTR + (((lane >> 3) & 1) << 4);

    const int nk = K >> 5;

    // prologue: stage chunks 0 and 1
#pragma unroll
    for (int p = 0; p < 2; ++p) {
        uint32_t sbuf = sb + p * BUF_SZ;
        size_t ko = (size_t)p * 64;
        cpa_stage<1>(sbuf,            gAh + ko, Kb, tid);
        cpa_stage<1>(sbuf + SZ_A,     gAl + ko, Kb, tid);
        cpa_stage<2>(sbuf + 2 * SZ_A, gB  + ko, Kb, tid);
        asm volatile("cp.async.commit_group;");
    }

    int buf = 0;
    int nbuf = 2;
    for (int kt = 0; kt < nk; ++kt) {
        asm volatile("cp.async.wait_group 1;");
        __syncthreads();

        if (kt + 2 < nk) {
            uint32_t sbuf = sb + nbuf * BUF_SZ;
            size_t ko = (size_t)(kt + 2) * 64;
            cpa_stage<1>(sbuf,            gAh + ko, Kb, tid);
            cpa_stage<1>(sbuf + SZ_A,     gAl + ko, Kb, tid);
            cpa_stage<2>(sbuf + 2 * SZ_A, gB  + ko, Kb, tid);
        }
        asm volatile("cp.async.commit_group;");

        const uint32_t sAh = sb + buf * BUF_SZ;
        const uint32_t sAl = sAh + SZ_A;
        const uint32_t sB  = sAh + 2 * SZ_A;

#pragma unroll
        for (int ks = 0; ks < 2; ++ks) {
            const uint32_t kb = ks * 32;
            uint32_t ah[2][4], al[2][4];
#pragma unroll
            for (int mt = 0; mt < 2; ++mt) {
                uint32_t base = (wm + mt * 16) * SSTR + aoff + kb;
                ldsm4(ah[mt][0], ah[mt][1], ah[mt][2], ah[mt][3], sAh + base);
                ldsm4(al[mt][0], al[mt][1], al[mt][2], al[mt][3], sAl + base);
            }
#pragma unroll
            for (int pr = 0; pr < 4; ++pr) {
                uint32_t bbase = (wn + pr * 16) * SSTR + boff + kb;
                uint32_t h0, h1, h2, h3;
                ldsm4(h0, h1, h2, h3, sB + bbase);
                uint32_t b0[2] = {h0, h1}, b1[2] = {h2, h3};
#pragma unroll
                for (int mt = 0; mt < 2; ++mt) {
                    mma16816(acc[mt][2 * pr],     ah[mt], b0);
                    mma16816(acc[mt][2 * pr + 1], ah[mt], b1);
                    mma16816(acc[mt][2 * pr],     al[mt], b0);
                    mma16816(acc[mt][2 * pr + 1], al[mt], b1);
                }
            }
        }
        buf  = (buf  + 1 == NSTAGE) ? 0 : buf  + 1;
        nbuf = (nbuf + 1 == NSTAGE) ? 0 : nbuf + 1;
    }

    const int g  = lane >> 2;
    const int tg = lane & 3;
#pragma unroll
    for (int mt = 0; mt < 2; ++mt) {
#pragma unroll
        for (int nt = 0; nt < 8; ++nt) {
            const float* d = acc[mt][nt];
            size_t r = (size_t)(bm + wm + mt * 16 + g) * N + bn + wn + nt * 8 + tg * 2;
            *(float2*)&C[r] = make_float2(d[0], d[1]);
            *(float2*)&C[r + 8 * (size_t)N] = make_float2(d[2], d[3]);
        }
    }
}

// ---------------- tiled small GEMM: ba = h @ W_ba (2048x64, K=2048) ----------------
__global__ __launch_bounds__(256) void gemm_ba(
    const float* __restrict__ A, const float* __restrict__ B, float* __restrict__ C)
{
    __shared__ float sh[64][65];
    __shared__ float sB[64][65];
    const int tid = threadIdx.x;
    const int col = tid & 63;
    const int rg  = tid >> 6;
    const int br  = blockIdx.x * 64;

    float acc[16];
#pragma unroll
    for (int r = 0; r < 16; ++r) acc[r] = 0.0f;

    for (int kt = 0; kt < HID / 64; ++kt) {
#pragma unroll
        for (int i = 0; i < 16; ++i) {
            int idx = tid + i * 256;
            int row = idx >> 6, kk = idx & 63;
            sh[row][kk] = A[(size_t)(br + row) * HID + kt * 64 + kk];
            sB[row][kk] = B[(size_t)(kt * 64 + row) * 64 + kk];
        }
        __syncthreads();
#pragma unroll 16
        for (int kk = 0; kk < 64; ++kk) {
            float b = sB[kk][col];
#pragma unroll
            for (int r = 0; r < 16; ++r)
                acc[r] = fmaf(sh[rg * 16 + r][kk], b, acc[r]);
        }
        __syncthreads();
    }
#pragma unroll
    for (int r = 0; r < 16; ++r)
        C[(size_t)(br + rg * 16 + r) * 64 + col] = acc[r];
}

// ---------------- causal depthwise conv (K=4) + SiLU, 4 t per thread ----------------
__global__ __launch_bounds__(256) void conv_silu(
    const float* __restrict__ qkvz, const float* __restrict__ conv_w,
    float* __restrict__ out)
{
    int idx = blockIdx.x * blockDim.x + threadIdx.x;
    if (idx >= (T_SEQ / 4) * CONV_DIM) return;
    int tq = idx >> 13;
    int c  = idx & (CONV_DIM - 1);
    int t0 = tq * 4;
    const float* w = conv_w + c * 4;
    float xv[7];
#pragma unroll
    for (int j = 0; j < 7; ++j) {
        int tt = t0 - 3 + j;
        xv[j] = (tt >= 0) ? qkvz[(size_t)tt * QKVZ_N + c] : 0.0f;
    }
#pragma unroll
    for (int i = 0; i < 4; ++i) {
        float a = w[0] * xv[i];
        a = fmaf(w[1], xv[i + 1], a);
        a = fmaf(w[2], xv[i + 2], a);
        a = fmaf(w[3], xv[i + 3], a);
        out[(size_t)(t0 + i) * CONV_DIM + c] = siluf_(a);
    }
}

// ---------------- gating ----------------
__global__ __launch_bounds__(256) void gate_prep(
    const float* __restrict__ ba, const float* __restrict__ A_log,
    const float* __restrict__ dt_bias, float2* __restrict__ egbeta)
{
    int i = blockIdx.x * blockDim.x + threadIdx.x;
    if (i >= T_SEQ * NUM_V) return;
    int t = i >> 5;
    int h = i & 31;
    float b = ba[(size_t)t * 64 + h];
    float a = ba[(size_t)t * 64 + 32 + h];
    float x = a + dt_bias[h];
    float sp = (x > 20.0f) ? x : log1pf(expf(x));
    float g = -expf(A_log[h]) * sp;
    egbeta[i] = make_float2(expf(g), sigmoidf_(b));
}

// ---------------- fused l2norm(q,k) + qk dot: one warp per (t, key-head) ----------------
__global__ __launch_bounds__(256) void l2norm_qk_dot(
    const float* __restrict__ qkv, float* __restrict__ qhat,
    float* __restrict__ khat, float* __restrict__ qkdot)
{
    int gid  = blockIdx.x * 8 + (threadIdx.x >> 5);
    int lane = threadIdx.x & 31;
    int t  = gid >> 4;
    int kh = gid & 15;
    const float* qsrc = qkv + (size_t)t * CONV_DIM + kh * DK;
    float4 q = *((const float4*)qsrc + lane);
    float4 k = *((const float4*)(qsrc + KEY_DIM) + lane);
    float sq  = q.x * q.x + q.y * q.y + q.z * q.z + q.w * q.w;
    float sk  = k.x * k.x + k.y * k.y + k.z * k.z + k.w * k.w;
    float sqk = q.x * k.x + q.y * k.y + q.z * k.z + q.w * k.w;
#pragma unroll
    for (int off = 16; off > 0; off >>= 1) {
        sq  += __shfl_xor_sync(0xffffffffu, sq,  off);
        sk  += __shfl_xor_sync(0xffffffffu, sk,  off);
        sqk += __shfl_xor_sync(0xffffffffu, sqk, off);
    }
    float rq = rsqrtf(sq + 1e-6f) * QSCALE;
    float rk = rsqrtf(sk + 1e-6f);
    size_t base = (size_t)t * KEY_DIM + kh * DK;
    *((float4*)(qhat + base) + lane) = make_float4(q.x * rq, q.y * rq, q.z * rq, q.w * rq);
    *((float4*)(khat + base) + lane) = make_float4(k.x * rk, k.y * rk, k.z * rk, k.w * rk);
    if (lane == 0) qkdot[t * NUM_K + kh] = sqk * rq * rk;
}

// ---------------- gated delta scan: one warp per (head, v-column), depth-1 prefetch ----------------
__global__ __launch_bounds__(256) void gdn_scan(
    const float* __restrict__ qhat, const float* __restrict__ khat,
    const float* __restrict__ qkv, const float2* __restrict__ egbeta,
    const float* __restrict__ qk, float* __restrict__ o)
{
    const int warp = threadIdx.x >> 5;
    const int lane = threadIdx.x & 31;
    const int h   = blockIdx.x >> 4;
    const int col = ((blockIdx.x & 15) << 3) + warp;
    const int kh  = h >> 1;

    const float4* kp = (const float4*)(khat + kh * DK) + lane;
    const float4* qp = (const float4*)(qhat + kh * DK) + lane;
    const float*  vp = qkv + 2 * KEY_DIM + h * DV + col;
    const float2* ep = egbeta + h;
    const float*  xp = qk + kh;
    float*        op = o + h * DV + col;

    float S0 = 0.f, S1 = 0.f, S2 = 0.f, S3 = 0.f;

    float4 kk = *kp, qq = *qp;
    float  vt = *vp, xq = *xp;
    float2 eb = *ep;

    for (int t = 0; t < T_SEQ; ++t) {
        float4 kk_n, qq_n; float vt_n, xq_n; float2 eb_n;
        if (t < T_SEQ - 1) {
            kp += KEY_DIM / 4; qp += KEY_DIM / 4; vp += CONV_DIM; ep += NUM_V; xp += NUM_K;
            kk_n = *kp; qq_n = *qp; vt_n = *vp; eb_n = *ep; xq_n = *xp;
        } else {
            kk_n = kk; qq_n = qq; vt_n = vt; eb_n = eb; xq_n = xq;
        }

        float dk = kk.x * S0 + kk.y * S1 + kk.z * S2 + kk.w * S3;
        float dq = qq.x * S0 + qq.y * S1 + qq.z * S2 + qq.w * S3;
#pragma unroll
        for (int off = 16; off > 0; off >>= 1) {
            dk += __shfl_xor_sync(0xffffffffu, dk, off);
            dq += __shfl_xor_sync(0xffffffffu, dq, off);
        }
        const float eg = eb.x, beta = eb.y;
        const float delta = (vt - eg * dk) * beta;
        const float ot    = fmaf(eg, dq, xq * delta);
        S0 = fmaf(S0, eg, kk.x * delta);
        S1 = fmaf(S1, eg, kk.y * delta);
        S2 = fmaf(S2, eg, kk.z * delta);
        S3 = fmaf(S3, eg, kk.w * delta);
        if (lane == 0) *op = ot;
        op += VAL_DIM;
        kk = kk_n; qq = qq_n; vt = vt_n; eb = eb_n; xq = xq_n;
    }
}

// ---------------- RMSNorm * norm_w * silu(z), write fp16 hi/lo directly ----------------
__global__ __launch_bounds__(256) void rms_gate_split(
    const float* __restrict__ o, const float* __restrict__ qkvz,
    const float* __restrict__ norm_w,
    __half* __restrict__ hi, __half* __restrict__ lo)
{
    int gid  = blockIdx.x * 8 + (threadIdx.x >> 5);
    int lane = threadIdx.x & 31;
    int t = gid >> 5;
    int h = gid & 31;
    const float* orow = o + (size_t)t * VAL_DIM + h * DV;
    float4 x = *(const float4*)(orow + lane * 4);
    float s = x.x * x.x + x.y * x.y + x.z * x.z + x.w * x.w;
#pragma unroll
    for (int off = 16; off > 0; off >>= 1) s += __shfl_xor_sync(0xffffffffu, s, off);
    float r = rsqrtf(s * (1.0f / DV) + 1e-6f);
    float4 z  = *(const float4*)(qkvz + (size_t)t * QKVZ_N + 2 * KEY_DIM + VAL_DIM + h * DV + lane * 4);
    float4 nw = *(const float4*)(norm_w + lane * 4);
    float4 y;
    y.x = x.x * r * nw.x * siluf_(z.x);
    y.y = x.y * r * nw.y * siluf_(z.y);
    y.z = x.z * r * nw.z * siluf_(z.z);
    y.w = x.w * r * nw.w * siluf_(z.w);
    __half h0 = __float2half_rn(y.x), h1 = __float2half_rn(y.y);
    __half h2 = __float2half_rn(y.z), h3 = __float2half_rn(y.w);
    __half l0 = __float2half_rn(y.x - __half2float(h0));
    __half l1 = __float2half_rn(y.y - __half2float(h1));
    __half l2 = __float2half_rn(y.z - __half2float(h2));
    __half l3 = __float2half_rn(y.w - __half2float(h3));
    union { __half2 h2v[2]; uint2 u; } H, L;
    H.h2v[0] = __halves2half2(h0, h1); H.h2v[1] = __halves2half2(h2, h3);
    L.h2v[0] = __halves2half2(l0, l1); L.h2v[1] = __halves2half2(l2, l3);
    int i4 = (t * VAL_DIM + h * DV) / 4 + lane;
    ((uint2*)hi)[i4] = H.u;
    ((uint2*)lo)[i4] = L.u;
}

// ---------------- launch ----------------
extern "C" void kernel_launch(void* const* d_in, const int* in_sizes, int n_in,
                              void* d_out, int out_size)
{
    const float* h_in    = (const float*)d_in[0];
    const float* W_qkvz  = (const float*)d_in[1];
    const float* W_ba    = (const float*)d_in[2];
    const float* conv_w  = (const float*)d_in[3];
    const float* dt_bias = (const float*)d_in[4];
    const float* A_log   = (const float*)d_in[5];
    const float* norm_w  = (const float*)d_in[6];
    const float* W_out   = (const float*)d_in[7];
    float* out = (float*)d_out;

    float *qkvz, *qkv, *ba, *qhat, *khat, *qkdot, *oscan;
    float2* egbeta;
    __half *Wq, *Wo, *A_hi, *A_lo;
    cudaGetSymbolAddress((void**)&qkvz,   g_qkvz);
    cudaGetSymbolAddress((void**)&qkv,    g_qkv);
    cudaGetSymbolAddress((void**)&ba,     g_ba);
    cudaGetSymbolAddress((void**)&egbeta, g_egbeta);
    cudaGetSymbolAddress((void**)&qhat,   g_qhat);
    cudaGetSymbolAddress((void**)&khat,   g_khat);
    cudaGetSymbolAddress((void**)&qkdot,  g_qkdot);
    cudaGetSymbolAddress((void**)&oscan,  g_oscan);
    cudaGetSymbolAddress((void**)&Wq,     g_Wq);
    cudaGetSymbolAddress((void**)&Wo,     g_Wo);
    cudaGetSymbolAddress((void**)&A_hi,   g_A_hi);
    cudaGetSymbolAddress((void**)&A_lo,   g_A_lo);

    cudaFuncSetAttribute(gemm_tc, cudaFuncAttributeMaxDynamicSharedMemorySize, GT_SMEM);

    // prep
    {
        dim3 blk(32, 8);
        tr_half<<<dim3(QKVZ_N / 32, HID / 32), blk>>>(W_qkvz, Wq, HID, QKVZ_N);
        tr_half<<<dim3(HID / 32, VAL_DIM / 32), blk>>>(W_out, Wo, VAL_DIM, HID);
    }
    cvt_split<<<(T_SEQ * HID / 4 + 255) / 256, 256>>>(h_in, A_hi, A_lo, T_SEQ * HID / 4);

    // GEMM1: qkvz = h @ W_qkvz   [2048 x 12288], K=2048
    gemm_tc<<<dim3(T_SEQ / 128, QKVZ_N / 256), 512, GT_SMEM>>>(A_hi, A_lo, Wq, qkvz, QKVZ_N, HID);

    gemm_ba<<<T_SEQ / 64, 256>>>(h_in, W_ba, ba);
    conv_silu<<<((T_SEQ / 4) * CONV_DIM) / 256, 256>>>(qkvz, conv_w, qkv);
    gate_prep<<<(T_SEQ * NUM_V) / 256, 256>>>(ba, A_log, dt_bias, egbeta);
    l2norm_qk_dot<<<(T_SEQ * NUM_K) / 8, 256>>>(qkv, qhat, khat, qkdot);
    gdn_scan<<<NUM_V * 16, 256>>>(qhat, khat, qkv, egbeta, qkdot, oscan);
    rms_gate_split<<<(T_SEQ * NUM_V) / 8, 256>>>(oscan, qkvz, norm_w, A_hi, A_lo);

    // GEMM2: out = gated @ W_out  [2048 x 2048], K=4096
    gemm_tc<<<dim3(T_SEQ / 128, HID / 256), 512, GT_SMEM>>>(A_hi, A_lo, Wo, out, HID, VAL_DIM);
}

// round 11
// speedup vs baseline: 1.0723x; 1.0266x over previous
#include <cuda_runtime.h>
#include <cuda_fp16.h>
#include <math.h>
#include <stdint.h>

// ---------------- problem constants ----------------
#define T_SEQ   2048
#define HID     2048
#define NUM_K   16
#define NUM_V   32
#define DK      128
#define DV      128
#define KEY_DIM 2048
#define VAL_DIM 4096
#define CONV_DIM 8192
#define QKVZ_N  12288
#define QSCALE  0.08838834764831845f

// ---------------- scratch ----------------
__device__ float  g_qkvz  [T_SEQ * QKVZ_N];
__device__ float  g_qkv   [T_SEQ * CONV_DIM];
__device__ float  g_ba    [T_SEQ * 64];
__device__ float2 g_egbeta[T_SEQ * NUM_V];
__device__ float  g_qhat  [T_SEQ * KEY_DIM];
__device__ float  g_khat  [T_SEQ * KEY_DIM];
__device__ float  g_qkdot [T_SEQ * NUM_K];
__device__ float  g_oscan [T_SEQ * VAL_DIM];

// fp16 operands: weights single fp16 (W^T), activations split hi/lo
__device__ __half g_Wq[QKVZ_N * HID];
__device__ __half g_Wo[HID * VAL_DIM];
__device__ __half g_A_hi[T_SEQ * VAL_DIM];
__device__ __half g_A_lo[T_SEQ * VAL_DIM];

// ---------------- helpers ----------------
__device__ __forceinline__ float sigmoidf_(float x) { return 1.0f / (1.0f + __expf(-x)); }
__device__ __forceinline__ float siluf_(float x)    { return x * sigmoidf_(x); }

__device__ __forceinline__ uint32_t smem_to_u32(const void* p) {
    uint32_t a;
    asm("{ .reg .u64 t; cvta.to.shared.u64 t, %1; cvt.u32.u64 %0, t; }" : "=r"(a) : "l"(p));
    return a;
}
__device__ __forceinline__ void ldsm4(uint32_t& r0, uint32_t& r1, uint32_t& r2, uint32_t& r3,
                                      uint32_t addr) {
    asm volatile("ldmatrix.sync.aligned.m8n8.x4.shared.b16 {%0,%1,%2,%3}, [%4];"
                 : "=r"(r0), "=r"(r1), "=r"(r2), "=r"(r3) : "r"(addr));
}
__device__ __forceinline__ void mma16816(float* d, const uint32_t* a, const uint32_t* b) {
    asm volatile("mma.sync.aligned.m16n8k16.row.col.f32.f16.f16.f32 "
                 "{%0,%1,%2,%3}, {%4,%5,%6,%7}, {%8,%9}, {%0,%1,%2,%3};"
                 : "+f"(d[0]), "+f"(d[1]), "+f"(d[2]), "+f"(d[3])
                 : "r"(a[0]), "r"(a[1]), "r"(a[2]), "r"(a[3]), "r"(b[0]), "r"(b[1]));
}

// ---------------- prep: fp32 -> fp16 hi/lo split ----------------
__global__ __launch_bounds__(256) void cvt_split(
    const float* __restrict__ x, __half* __restrict__ hi,
    __half* __restrict__ lo, int n4)
{
    int i = blockIdx.x * 256 + threadIdx.x;
    if (i >= n4) return;
    float4 v = ((const float4*)x)[i];
    __half h0 = __float2half_rn(v.x), h1 = __float2half_rn(v.y);
    __half h2 = __float2half_rn(v.z), h3 = __float2half_rn(v.w);
    __half l0 = __float2half_rn(v.x - __half2float(h0));
    __half l1 = __float2half_rn(v.y - __half2float(h1));
    __half l2 = __float2half_rn(v.z - __half2float(h2));
    __half l3 = __float2half_rn(v.w - __half2float(h3));
    union { __half2 h2v[2]; uint2 u; } H, L;
    H.h2v[0] = __halves2half2(h0, h1); H.h2v[1] = __halves2half2(h2, h3);
    L.h2v[0] = __halves2half2(l0, l1); L.h2v[1] = __halves2half2(l2, l3);
    ((uint2*)hi)[i] = H.u;
    ((uint2*)lo)[i] = L.u;
}

// ---------------- prep: W [K][N] fp32 -> W^T [N][K] fp16 ----------------
__global__ __launch_bounds__(256) void tr_half(
    const float* __restrict__ W, __half* __restrict__ out, int K, int N)
{
    __shared__ float t[32][33];
    int n0 = blockIdx.x * 32, k0 = blockIdx.y * 32;
    int tx = threadIdx.x, ty = threadIdx.y;
#pragma unroll
    for (int j = 0; j < 4; ++j)
        t[ty + j * 8][tx] = W[(size_t)(k0 + ty + j * 8) * N + n0 + tx];
    __syncthreads();
#pragma unroll
    for (int j = 0; j < 4; ++j) {
        int n = ty + j * 8;
        out[(size_t)(n0 + n) * K + k0 + tx] = __float2half_rn(t[tx][n]);
    }
}

// ---------------- mma.sync GEMM: 128x256 CTA, 512 threads, BK=64, 2-stage ----------------
#define SSTR   144                       // 128B row + 16B pad
#define SZ_A   (128 * SSTR)              // 18432
#define SZ_B   (256 * SSTR)              // 36864
#define BUF_SZ (2 * SZ_A + SZ_B)         // 73728
#define NSTAGE 2
#define GT_SMEM (NSTAGE * BUF_SZ)        // 147456

template<int ITERS>
__device__ __forceinline__ void cpa_stage(uint32_t sdst, const char* g, int Kb, int tid) {
#pragma unroll
    for (int i = 0; i < ITERS; ++i) {
        int idx = tid + i * 512;
        int row = idx >> 3;              // 8 uint4 per 128B row
        int q   = (idx & 7) << 4;
        uint32_t d = sdst + row * SSTR + q;
        const char* s = g + (size_t)row * Kb + q;
        asm volatile("cp.async.cg.shared.global [%0], [%1], 16;" :: "r"(d), "l"(s));
    }
}

__global__ __launch_bounds__(512, 1) void gemm_tc(
    const __half* __restrict__ Ahi, const __half* __restrict__ Alo,
    const __half* __restrict__ B, float* __restrict__ C, int N, int K)
{
    extern __shared__ __align__(128) char smem[];
    const uint32_t sb = smem_to_u32(smem);

    const int tid  = threadIdx.x;
    const int wid  = tid >> 5;
    const int lane = tid & 31;
    const int bm   = blockIdx.x * 128;
    const int bn   = blockIdx.y * 256;
    const int wm   = (wid >> 2) * 32;
    const int wn   = (wid & 3) * 64;
    const int Kb   = K * 2;

    const char* gAh = (const char*)(Ahi + (size_t)bm * K);
    const char* gAl = (const char*)(Alo + (size_t)bm * K);
    const char* gB  = (const char*)(B   + (size_t)bn * K);

    float acc[2][8][4];
#pragma unroll
    for (int i = 0; i < 2; ++i)
#pragma unroll
        for (int j = 0; j < 8; ++j)
#pragma unroll
            for (int r = 0; r < 4; ++r) acc[i][j][r] = 0.0f;

    const uint32_t aoff = (lane & 15) * SSTR + ((lane >> 4) << 4);
    const uint32_t boff = ((lane & 7) + ((lane >> 4) << 3)) * SSTR + (((lane >> 3) & 1) << 4);

    const int nk = K >> 6;               // BK = 64

    // prologue: stage chunk 0
    {
        uint32_t sbuf = sb;
        cpa_stage<2>(sbuf,            gAh, Kb, tid);
        cpa_stage<2>(sbuf + SZ_A,     gAl, Kb, tid);
        cpa_stage<4>(sbuf + 2 * SZ_A, gB,  Kb, tid);
        asm volatile("cp.async.commit_group;");
    }

    for (int kt = 0; kt < nk; ++kt) {
        asm volatile("cp.async.wait_group 0;");
        __syncthreads();

        // stage kt+1 into the other buffer (race-free: sync above ordered
        // all compute on that buffer from iteration kt-1)
        if (kt + 1 < nk) {
            uint32_t sbuf = sb + ((kt + 1) & 1) * BUF_SZ;
            size_t ko = (size_t)(kt + 1) * 128;    // 64 halves = 128 bytes
            cpa_stage<2>(sbuf,            gAh + ko, Kb, tid);
            cpa_stage<2>(sbuf + SZ_A,     gAl + ko, Kb, tid);
            cpa_stage<4>(sbuf + 2 * SZ_A, gB  + ko, Kb, tid);
            asm volatile("cp.async.commit_group;");
        }

        const uint32_t sAh = sb + (kt & 1) * BUF_SZ;
        const uint32_t sAl = sAh + SZ_A;
        const uint32_t sB  = sAh + 2 * SZ_A;

#pragma unroll
        for (int ks = 0; ks < 4; ++ks) {
            const uint32_t kb = ks * 32;
            uint32_t ah[2][4], al[2][4];
#pragma unroll
            for (int mt = 0; mt < 2; ++mt) {
                uint32_t base = (wm + mt * 16) * SSTR + aoff + kb;
                ldsm4(ah[mt][0], ah[mt][1], ah[mt][2], ah[mt][3], sAh + base);
                ldsm4(al[mt][0], al[mt][1], al[mt][2], al[mt][3], sAl + base);
            }
#pragma unroll
            for (int pr = 0; pr < 4; ++pr) {
                uint32_t bbase = (wn + pr * 16) * SSTR + boff + kb;
                uint32_t h0, h1, h2, h3;
                ldsm4(h0, h1, h2, h3, sB + bbase);
                uint32_t b0[2] = {h0, h1}, b1[2] = {h2, h3};
#pragma unroll
                for (int mt = 0; mt < 2; ++mt) {
                    mma16816(acc[mt][2 * pr],     ah[mt], b0);
                    mma16816(acc[mt][2 * pr + 1], ah[mt], b1);
                    mma16816(acc[mt][2 * pr],     al[mt], b0);
                    mma16816(acc[mt][2 * pr + 1], al[mt], b1);
                }
            }
        }
    }

    const int g  = lane >> 2;
    const int tg = lane & 3;
#pragma unroll
    for (int mt = 0; mt < 2; ++mt) {
#pragma unroll
        for (int nt = 0; nt < 8; ++nt) {
            const float* d = acc[mt][nt];
            size_t r = (size_t)(bm + wm + mt * 16 + g) * N + bn + wn + nt * 8 + tg * 2;
            *(float2*)&C[r] = make_float2(d[0], d[1]);
            *(float2*)&C[r + 8 * (size_t)N] = make_float2(d[2], d[3]);
        }
    }
}

// ---------------- tiled small GEMM: ba = h @ W_ba (2048x64, K=2048) ----------------
__global__ __launch_bounds__(256) void gemm_ba(
    const float* __restrict__ A, const float* __restrict__ B, float* __restrict__ C)
{
    __shared__ float sh[64][65];
    __shared__ float sB[64][65];
    const int tid = threadIdx.x;
    const int col = tid & 63;
    const int rg  = tid >> 6;
    const int br  = blockIdx.x * 64;

    float acc[16];
#pragma unroll
    for (int r = 0; r < 16; ++r) acc[r] = 0.0f;

    for (int kt = 0; kt < HID / 64; ++kt) {
#pragma unroll
        for (int i = 0; i < 16; ++i) {
            int idx = tid + i * 256;
            int row = idx >> 6, kk = idx & 63;
            sh[row][kk] = A[(size_t)(br + row) * HID + kt * 64 + kk];
            sB[row][kk] = B[(size_t)(kt * 64 + row) * 64 + kk];
        }
        __syncthreads();
#pragma unroll 16
        for (int kk = 0; kk < 64; ++kk) {
            float b = sB[kk][col];
#pragma unroll
            for (int r = 0; r < 16; ++r)
                acc[r] = fmaf(sh[rg * 16 + r][kk], b, acc[r]);
        }
        __syncthreads();
    }
#pragma unroll
    for (int r = 0; r < 16; ++r)
        C[(size_t)(br + rg * 16 + r) * 64 + col] = acc[r];
}

// ---------------- causal depthwise conv (K=4) + SiLU, 4 t per thread ----------------
__global__ __launch_bounds__(256) void conv_silu(
    const float* __restrict__ qkvz, const float* __restrict__ conv_w,
    float* __restrict__ out)
{
    int idx = blockIdx.x * blockDim.x + threadIdx.x;
    if (idx >= (T_SEQ / 4) * CONV_DIM) return;
    int tq = idx >> 13;
    int c  = idx & (CONV_DIM - 1);
    int t0 = tq * 4;
    const float* w = conv_w + c * 4;
    float xv[7];
#pragma unroll
    for (int j = 0; j < 7; ++j) {
        int tt = t0 - 3 + j;
        xv[j] = (tt >= 0) ? qkvz[(size_t)tt * QKVZ_N + c] : 0.0f;
    }
#pragma unroll
    for (int i = 0; i < 4; ++i) {
        float a = w[0] * xv[i];
        a = fmaf(w[1], xv[i + 1], a);
        a = fmaf(w[2], xv[i + 2], a);
        a = fmaf(w[3], xv[i + 3], a);
        out[(size_t)(t0 + i) * CONV_DIM + c] = siluf_(a);
    }
}

// ---------------- gating ----------------
__global__ __launch_bounds__(256) void gate_prep(
    const float* __restrict__ ba, const float* __restrict__ A_log,
    const float* __restrict__ dt_bias, float2* __restrict__ egbeta)
{
    int i = blockIdx.x * blockDim.x + threadIdx.x;
    if (i >= T_SEQ * NUM_V) return;
    int t = i >> 5;
    int h = i & 31;
    float b = ba[(size_t)t * 64 + h];
    float a = ba[(size_t)t * 64 + 32 + h];
    float x = a + dt_bias[h];
    float sp = (x > 20.0f) ? x : log1pf(expf(x));
    float g = -expf(A_log[h]) * sp;
    egbeta[i] = make_float2(expf(g), sigmoidf_(b));
}

// ---------------- fused l2norm(q,k) + qk dot: one warp per (t, key-head) ----------------
__global__ __launch_bounds__(256) void l2norm_qk_dot(
    const float* __restrict__ qkv, float* __restrict__ qhat,
    float* __restrict__ khat, float* __restrict__ qkdot)
{
    int gid  = blockIdx.x * 8 + (threadIdx.x >> 5);
    int lane = threadIdx.x & 31;
    int t  = gid >> 4;
    int kh = gid & 15;
    const float* qsrc = qkv + (size_t)t * CONV_DIM + kh * DK;
    float4 q = *((const float4*)qsrc + lane);
    float4 k = *((const float4*)(qsrc + KEY_DIM) + lane);
    float sq  = q.x * q.x + q.y * q.y + q.z * q.z + q.w * q.w;
    float sk  = k.x * k.x + k.y * k.y + k.z * k.z + k.w * k.w;
    float sqk = q.x * k.x + q.y * k.y + q.z * k.z + q.w * k.w;
#pragma unroll
    for (int off = 16; off > 0; off >>= 1) {
        sq  += __shfl_xor_sync(0xffffffffu, sq,  off);
        sk  += __shfl_xor_sync(0xffffffffu, sk,  off);
        sqk += __shfl_xor_sync(0xffffffffu, sqk, off);
    }
    float rq = rsqrtf(sq + 1e-6f) * QSCALE;
    float rk = rsqrtf(sk + 1e-6f);
    size_t base = (size_t)t * KEY_DIM + kh * DK;
    *((float4*)(qhat + base) + lane) = make_float4(q.x * rq, q.y * rq, q.z * rq, q.w * rq);
    *((float4*)(khat + base) + lane) = make_float4(k.x * rk, k.y * rk, k.z * rk, k.w * rk);
    if (lane == 0) qkdot[t * NUM_K + kh] = sqk * rq * rk;
}

// ---------------- gated delta scan: 2 columns/warp (16 lanes each, 8 dims/lane) ----------------
__global__ __launch_bounds__(256) void gdn_scan(
    const float* __restrict__ qhat, const float* __restrict__ khat,
    const float* __restrict__ qkv, const float2* __restrict__ egbeta,
    const float* __restrict__ qk, float* __restrict__ o)
{
    const int warp = threadIdx.x >> 5;
    const int lane = threadIdx.x & 31;
    const int half = lane >> 4;                       // 0/1 -> column select
    const int sl   = lane & 15;                       // sublane within column group
    const int h    = blockIdx.x >> 3;                 // 32 heads x 8 blocks
    const int col  = ((blockIdx.x & 7) * 8 + warp) * 2 + half;
    const int kh   = h >> 1;

    const float4* kp = (const float4*)(khat + kh * DK) + sl * 2;  // dims sl*8..sl*8+7
    const float4* qp = (const float4*)(qhat + kh * DK) + sl * 2;
    const float*  vp = qkv + 2 * KEY_DIM + h * DV + col;
    const float2* ep = egbeta + h;
    const float*  xp = qk + kh;
    float*        op = o + h * DV + col;

    const int SK = KEY_DIM / 4;

    float4 Sa = make_float4(0.f, 0.f, 0.f, 0.f);
    float4 Sb = make_float4(0.f, 0.f, 0.f, 0.f);

    float4 k0 = kp[0], k1 = kp[1], q0 = qp[0], q1 = qp[1];
    float  vt = *vp, xq = *xp;
    float2 eb = *ep;

    for (int t = 0; t < T_SEQ; ++t) {
        float4 k0n, k1n, q0n, q1n; float vtn, xqn; float2 ebn;
        if (t < T_SEQ - 1) {
            kp += SK; qp += SK; vp += CONV_DIM; ep += NUM_V; xp += NUM_K;
            k0n = kp[0]; k1n = kp[1]; q0n = qp[0]; q1n = qp[1];
            vtn = *vp; ebn = *ep; xqn = *xp;
        } else {
            k0n = k0; k1n = k1; q0n = q0; q1n = q1; vtn = vt; ebn = eb; xqn = xq;
        }

        float dk = k0.x * Sa.x + k0.y * Sa.y + k0.z * Sa.z + k0.w * Sa.w
                 + k1.x * Sb.x + k1.y * Sb.y + k1.z * Sb.z + k1.w * Sb.w;
        float dq = q0.x * Sa.x + q0.y * Sa.y + q0.z * Sa.z + q0.w * Sa.w
                 + q1.x * Sb.x + q1.y * Sb.y + q1.z * Sb.z + q1.w * Sb.w;
#pragma unroll
        for (int off = 8; off > 0; off >>= 1) {
            dk += __shfl_xor_sync(0xffffffffu, dk, off);
            dq += __shfl_xor_sync(0xffffffffu, dq, off);
        }
        const float eg = eb.x, beta = eb.y;
        const float delta = (vt - eg * dk) * beta;
        const float ot    = fmaf(eg, dq, xq * delta);
        Sa.x = fmaf(Sa.x, eg, k0.x * delta);
        Sa.y = fmaf(Sa.y, eg, k0.y * delta);
        Sa.z = fmaf(Sa.z, eg, k0.z * delta);
        Sa.w = fmaf(Sa.w, eg, k0.w * delta);
        Sb.x = fmaf(Sb.x, eg, k1.x * delta);
        Sb.y = fmaf(Sb.y, eg, k1.y * delta);
        Sb.z = fmaf(Sb.z, eg, k1.z * delta);
        Sb.w = fmaf(Sb.w, eg, k1.w * delta);
        if (sl == 0) *op = ot;
        op += VAL_DIM;
        k0 = k0n; k1 = k1n; q0 = q0n; q1 = q1n; vt = vtn; eb = ebn; xq = xqn;
    }
}

// ---------------- RMSNorm * norm_w * silu(z), write fp16 hi/lo directly ----------------
__global__ __launch_bounds__(256) void rms_gate_split(
    const float* __restrict__ o, const float* __restrict__ qkvz,
    const float* __restrict__ norm_w,
    __half* __restrict__ hi, __half* __restrict__ lo)
{
    int gid  = blockIdx.x * 8 + (threadIdx.x >> 5);
    int lane = threadIdx.x & 31;
    int t = gid >> 5;
    int h = gid & 31;
    const float* orow = o + (size_t)t * VAL_DIM + h * DV;
    float4 x = *(const float4*)(orow + lane * 4);
    float s = x.x * x.x + x.y * x.y + x.z * x.z + x.w * x.w;
#pragma unroll
    for (int off = 16; off > 0; off >>= 1) s += __shfl_xor_sync(0xffffffffu, s, off);
    float r = rsqrtf(s * (1.0f / DV) + 1e-6f);
    float4 z  = *(const float4*)(qkvz + (size_t)t * QKVZ_N + 2 * KEY_DIM + VAL_DIM + h * DV + lane * 4);
    float4 nw = *(const float4*)(norm_w + lane * 4);
    float4 y;
    y.x = x.x * r * nw.x * siluf_(z.x);
    y.y = x.y * r * nw.y * siluf_(z.y);
    y.z = x.z * r * nw.z * siluf_(z.z);
    y.w = x.w * r * nw.w * siluf_(z.w);
    __half h0 = __float2half_rn(y.x), h1 = __float2half_rn(y.y);
    __half h2 = __float2half_rn(y.z), h3 = __float2half_rn(y.w);
    __half l0 = __float2half_rn(y.x - __half2float(h0));
    __half l1 = __float2half_rn(y.y - __half2float(h1));
    __half l2 = __float2half_rn(y.z - __half2float(h2));
    __half l3 = __float2half_rn(y.w - __half2float(h3));
    union { __half2 h2v[2]; uint2 u; } H, L;
    H.h2v[0] = __halves2half2(h0, h1); H.h2v[1] = __halves2half2(h2, h3);
    L.h2v[0] = __halves2half2(l0, l1); L.h2v[1] = __halves2half2(l2, l3);
    int i4 = (t * VAL_DIM + h * DV) / 4 + lane;
    ((uint2*)hi)[i4] = H.u;
    ((uint2*)lo)[i4] = L.u;
}

// ---------------- launch ----------------
extern "C" void kernel_launch(void* const* d_in, const int* in_sizes, int n_in,
                              void* d_out, int out_size)
{
    const float* h_in    = (const float*)d_in[0];
    const float* W_qkvz  = (const float*)d_in[1];
    const float* W_ba    = (const float*)d_in[2];
    const float* conv_w  = (const float*)d_in[3];
    const float* dt_bias = (const float*)d_in[4];
    const float* A_log   = (const float*)d_in[5];
    const float* norm_w  = (const float*)d_in[6];
    const float* W_out   = (const float*)d_in[7];
    float* out = (float*)d_out;

    float *qkvz, *qkv, *ba, *qhat, *khat, *qkdot, *oscan;
    float2* egbeta;
    __half *Wq, *Wo, *A_hi, *A_lo;
    cudaGetSymbolAddress((void**)&qkvz,   g_qkvz);
    cudaGetSymbolAddress((void**)&qkv,    g_qkv);
    cudaGetSymbolAddress((void**)&ba,     g_ba);
    cudaGetSymbolAddress((void**)&egbeta, g_egbeta);
    cudaGetSymbolAddress((void**)&qhat,   g_qhat);
    cudaGetSymbolAddress((void**)&khat,   g_khat);
    cudaGetSymbolAddress((void**)&qkdot,  g_qkdot);
    cudaGetSymbolAddress((void**)&oscan,  g_oscan);
    cudaGetSymbolAddress((void**)&Wq,     g_Wq);
    cudaGetSymbolAddress((void**)&Wo,     g_Wo);
    cudaGetSymbolAddress((void**)&A_hi,   g_A_hi);
    cudaGetSymbolAddress((void**)&A_lo,   g_A_lo);

    cudaFuncSetAttribute(gemm_tc, cudaFuncAttributeMaxDynamicSharedMemorySize, GT_SMEM);

    // prep
    {
        dim3 blk(32, 8);
        tr_half<<<dim3(QKVZ_N / 32, HID / 32), blk>>>(W_qkvz, Wq, HID, QKVZ_N);
        tr_half<<<dim3(HID / 32, VAL_DIM / 32), blk>>>(W_out, Wo, VAL_DIM, HID);
    }
    cvt_split<<<(T_SEQ * HID / 4 + 255) / 256, 256>>>(h_in, A_hi, A_lo, T_SEQ * HID / 4);

    // GEMM1: qkvz = h @ W_qkvz   [2048 x 12288], K=2048
    gemm_tc<<<dim3(T_SEQ / 128, QKVZ_N / 256), 512, GT_SMEM>>>(A_hi, A_lo, Wq, qkvz, QKVZ_N, HID);

    gemm_ba<<<T_SEQ / 64, 256>>>(h_in, W_ba, ba);
    conv_silu<<<((T_SEQ / 4) * CONV_DIM) / 256, 256>>>(qkvz, conv_w, qkv);
    gate_prep<<<(T_SEQ * NUM_V) / 256, 256>>>(ba, A_log, dt_bias, egbeta);
    l2norm_qk_dot<<<(T_SEQ * NUM_K) / 8, 256>>>(qkv, qhat, khat, qkdot);
    gdn_scan<<<NUM_V * 8, 256>>>(qhat, khat, qkv, egbeta, qkdot, oscan);
    rms_gate_split<<<(T_SEQ * NUM_V) / 8, 256>>>(oscan, qkvz, norm_w, A_hi, A_lo);

    // GEMM2: out = gated @ W_out  [2048 x 2048], K=4096
    gemm_tc<<<dim3(T_SEQ / 128, HID / 256), 512, GT_SMEM>>>(A_hi, A_lo, Wo, out, HID, VAL_DIM);
}

// round 12
// speedup vs baseline: 1.4919x; 1.3913x over previous
#include <cuda_runtime.h>
#include <cuda_fp16.h>
#include <math.h>
#include <stdint.h>

// ---------------- problem constants ----------------
#define T_SEQ   2048
#define HID     2048
#define NUM_K   16
#define NUM_V   32
#define DK      128
#define DV      128
#define KEY_DIM 2048
#define VAL_DIM 4096
#define CONV_DIM 8192
#define QKVZ_N  12288
#define QSCALE  0.08838834764831845f

// ---------------- scratch ----------------
__device__ float  g_qkvz  [T_SEQ * QKVZ_N];
__device__ float  g_qkv   [T_SEQ * CONV_DIM];
__device__ float  g_ba    [T_SEQ * 64];
__device__ float2 g_egbeta[T_SEQ * NUM_V];
__device__ float  g_qhat  [T_SEQ * KEY_DIM];
__device__ float  g_khat  [T_SEQ * KEY_DIM];
__device__ float  g_qkdot [T_SEQ * NUM_K];
__device__ float  g_oscan [T_SEQ * VAL_DIM];

// fp16 operands: weights single fp16 (W^T), activations split hi/lo
__device__ __half g_Wq[QKVZ_N * HID];
__device__ __half g_Wo[HID * VAL_DIM];
__device__ __half g_A_hi[T_SEQ * VAL_DIM];
__device__ __half g_A_lo[T_SEQ * VAL_DIM];

// ---------------- helpers ----------------
__device__ __forceinline__ float sigmoidf_(float x) { return 1.0f / (1.0f + __expf(-x)); }
__device__ __forceinline__ float siluf_(float x)    { return x * sigmoidf_(x); }

__device__ __forceinline__ uint32_t smem_to_u32(const void* p) {
    uint32_t a;
    asm("{ .reg .u64 t; cvta.to.shared.u64 t, %1; cvt.u32.u64 %0, t; }" : "=r"(a) : "l"(p));
    return a;
}
__device__ __forceinline__ void ldsm4(uint32_t& r0, uint32_t& r1, uint32_t& r2, uint32_t& r3,
                                      uint32_t addr) {
    asm volatile("ldmatrix.sync.aligned.m8n8.x4.shared.b16 {%0,%1,%2,%3}, [%4];"
                 : "=r"(r0), "=r"(r1), "=r"(r2), "=r"(r3) : "r"(addr));
}
__device__ __forceinline__ void mma16816(float* d, const uint32_t* a, const uint32_t* b) {
    asm volatile("mma.sync.aligned.m16n8k16.row.col.f32.f16.f16.f32 "
                 "{%0,%1,%2,%3}, {%4,%5,%6,%7}, {%8,%9}, {%0,%1,%2,%3};"
                 : "+f"(d[0]), "+f"(d[1]), "+f"(d[2]), "+f"(d[3])
                 : "r"(a[0]), "r"(a[1]), "r"(a[2]), "r"(a[3]), "r"(b[0]), "r"(b[1]));
}

// ---------------- prep: fp32 -> fp16 hi/lo split ----------------
__global__ __launch_bounds__(256) void cvt_split(
    const float* __restrict__ x, __half* __restrict__ hi,
    __half* __restrict__ lo, int n4)
{
    int i = blockIdx.x * 256 + threadIdx.x;
    if (i >= n4) return;
    float4 v = ((const float4*)x)[i];
    __half h0 = __float2half_rn(v.x), h1 = __float2half_rn(v.y);
    __half h2 = __float2half_rn(v.z), h3 = __float2half_rn(v.w);
    __half l0 = __float2half_rn(v.x - __half2float(h0));
    __half l1 = __float2half_rn(v.y - __half2float(h1));
    __half l2 = __float2half_rn(v.z - __half2float(h2));
    __half l3 = __float2half_rn(v.w - __half2float(h3));
    union { __half2 h2v[2]; uint2 u; } H, L;
    H.h2v[0] = __halves2half2(h0, h1); H.h2v[1] = __halves2half2(h2, h3);
    L.h2v[0] = __halves2half2(l0, l1); L.h2v[1] = __halves2half2(l2, l3);
    ((uint2*)hi)[i] = H.u;
    ((uint2*)lo)[i] = L.u;
}

// ---------------- prep: W [K][N] fp32 -> W^T [N][K] fp16 ----------------
__global__ __launch_bounds__(256) void tr_half(
    const float* __restrict__ W, __half* __restrict__ out, int K, int N)
{
    __shared__ float t[32][33];
    int n0 = blockIdx.x * 32, k0 = blockIdx.y * 32;
    int tx = threadIdx.x, ty = threadIdx.y;
#pragma unroll
    for (int j = 0; j < 4; ++j)
        t[ty + j * 8][tx] = W[(size_t)(k0 + ty + j * 8) * N + n0 + tx];
    __syncthreads();
#pragma unroll
    for (int j = 0; j < 4; ++j) {
        int n = ty + j * 8;
        out[(size_t)(n0 + n) * K + k0 + tx] = __float2half_rn(t[tx][n]);
    }
}

// ---------------- mma.sync GEMM: 128x256 CTA, 512 threads, BK=64, 2-stage ----------------
#define SSTR   144
#define SZ_A   (128 * SSTR)
#define SZ_B   (256 * SSTR)
#define BUF_SZ (2 * SZ_A + SZ_B)
#define GT_SMEM (2 * BUF_SZ)

template<int ITERS>
__device__ __forceinline__ void cpa_stage(uint32_t sdst, const char* g, int Kb, int tid) {
#pragma unroll
    for (int i = 0; i < ITERS; ++i) {
        int idx = tid + i * 512;
        int row = idx >> 3;
        int q   = (idx & 7) << 4;
        uint32_t d = sdst + row * SSTR + q;
        const char* s = g + (size_t)row * Kb + q;
        asm volatile("cp.async.cg.shared.global [%0], [%1], 16;" :: "r"(d), "l"(s));
    }
}

__global__ __launch_bounds__(512, 1) void gemm_tc(
    const __half* __restrict__ Ahi, const __half* __restrict__ Alo,
    const __half* __restrict__ B, float* __restrict__ C, int N, int K)
{
    extern __shared__ __align__(128) char smem[];
    const uint32_t sb = smem_to_u32(smem);

    const int tid  = threadIdx.x;
    const int wid  = tid >> 5;
    const int lane = tid & 31;
    const int bm   = blockIdx.x * 128;
    const int bn   = blockIdx.y * 256;
    const int wm   = (wid >> 2) * 32;
    const int wn   = (wid & 3) * 64;
    const int Kb   = K * 2;

    const char* gAh = (const char*)(Ahi + (size_t)bm * K);
    const char* gAl = (const char*)(Alo + (size_t)bm * K);
    const char* gB  = (const char*)(B   + (size_t)bn * K);

    float acc[2][8][4];
#pragma unroll
    for (int i = 0; i < 2; ++i)
#pragma unroll
        for (int j = 0; j < 8; ++j)
#pragma unroll
            for (int r = 0; r < 4; ++r) acc[i][j][r] = 0.0f;

    const uint32_t aoff = (lane & 15) * SSTR + ((lane >> 4) << 4);
    const uint32_t boff = ((lane & 7) + ((lane >> 4) << 3)) * SSTR + (((lane >> 3) & 1) << 4);

    const int nk = K >> 6;

    {
        uint32_t sbuf = sb;
        cpa_stage<2>(sbuf,            gAh, Kb, tid);
        cpa_stage<2>(sbuf + SZ_A,     gAl, Kb, tid);
        cpa_stage<4>(sbuf + 2 * SZ_A, gB,  Kb, tid);
        asm volatile("cp.async.commit_group;");
    }

    for (int kt = 0; kt < nk; ++kt) {
        asm volatile("cp.async.wait_group 0;");
        __syncthreads();

        if (kt + 1 < nk) {
            uint32_t sbuf = sb + ((kt + 1) & 1) * BUF_SZ;
            size_t ko = (size_t)(kt + 1) * 128;
            cpa_stage<2>(sbuf,            gAh + ko, Kb, tid);
            cpa_stage<2>(sbuf + SZ_A,     gAl + ko, Kb, tid);
            cpa_stage<4>(sbuf + 2 * SZ_A, gB  + ko, Kb, tid);
            asm volatile("cp.async.commit_group;");
        }

        const uint32_t sAh = sb + (kt & 1) * BUF_SZ;
        const uint32_t sAl = sAh + SZ_A;
        const uint32_t sB  = sAh + 2 * SZ_A;

#pragma unroll
        for (int ks = 0; ks < 4; ++ks) {
            const uint32_t kb = ks * 32;
            uint32_t ah[2][4], al[2][4];
#pragma unroll
            for (int mt = 0; mt < 2; ++mt) {
                uint32_t base = (wm + mt * 16) * SSTR + aoff + kb;
                ldsm4(ah[mt][0], ah[mt][1], ah[mt][2], ah[mt][3], sAh + base);
                ldsm4(al[mt][0], al[mt][1], al[mt][2], al[mt][3], sAl + base);
            }
#pragma unroll
            for (int pr = 0; pr < 4; ++pr) {
                uint32_t bbase = (wn + pr * 16) * SSTR + boff + kb;
                uint32_t h0, h1, h2, h3;
                ldsm4(h0, h1, h2, h3, sB + bbase);
                uint32_t b0[2] = {h0, h1}, b1[2] = {h2, h3};
#pragma unroll
                for (int mt = 0; mt < 2; ++mt) {
                    mma16816(acc[mt][2 * pr],     ah[mt], b0);
                    mma16816(acc[mt][2 * pr + 1], ah[mt], b1);
                    mma16816(acc[mt][2 * pr],     al[mt], b0);
                    mma16816(acc[mt][2 * pr + 1], al[mt], b1);
                }
            }
        }
    }

    const int g  = lane >> 2;
    const int tg = lane & 3;
#pragma unroll
    for (int mt = 0; mt < 2; ++mt) {
#pragma unroll
        for (int nt = 0; nt < 8; ++nt) {
            const float* d = acc[mt][nt];
            size_t r = (size_t)(bm + wm + mt * 16 + g) * N + bn + wn + nt * 8 + tg * 2;
            *(float2*)&C[r] = make_float2(d[0], d[1]);
            *(float2*)&C[r + 8 * (size_t)N] = make_float2(d[2], d[3]);
        }
    }
}

// ---------------- tiled small GEMM: ba = h @ W_ba (2048x64, K=2048) ----------------
__global__ __launch_bounds__(256) void gemm_ba(
    const float* __restrict__ A, const float* __restrict__ B, float* __restrict__ C)
{
    __shared__ float sh[64][65];
    __shared__ float sB[64][65];
    const int tid = threadIdx.x;
    const int col = tid & 63;
    const int rg  = tid >> 6;
    const int br  = blockIdx.x * 64;

    float acc[16];
#pragma unroll
    for (int r = 0; r < 16; ++r) acc[r] = 0.0f;

    for (int kt = 0; kt < HID / 64; ++kt) {
#pragma unroll
        for (int i = 0; i < 16; ++i) {
            int idx = tid + i * 256;
            int row = idx >> 6, kk = idx & 63;
            sh[row][kk] = A[(size_t)(br + row) * HID + kt * 64 + kk];
            sB[row][kk] = B[(size_t)(kt * 64 + row) * 64 + kk];
        }
        __syncthreads();
#pragma unroll 16
        for (int kk = 0; kk < 64; ++kk) {
            float b = sB[kk][col];
#pragma unroll
            for (int r = 0; r < 16; ++r)
                acc[r] = fmaf(sh[rg * 16 + r][kk], b, acc[r]);
        }
        __syncthreads();
    }
#pragma unroll
    for (int r = 0; r < 16; ++r)
        C[(size_t)(br + rg * 16 + r) * 64 + col] = acc[r];
}

// ---------------- causal depthwise conv (K=4) + SiLU, 4 t per thread ----------------
__global__ __launch_bounds__(256) void conv_silu(
    const float* __restrict__ qkvz, const float* __restrict__ conv_w,
    float* __restrict__ out)
{
    int idx = blockIdx.x * blockDim.x + threadIdx.x;
    if (idx >= (T_SEQ / 4) * CONV_DIM) return;
    int tq = idx >> 13;
    int c  = idx & (CONV_DIM - 1);
    int t0 = tq * 4;
    const float* w = conv_w + c * 4;
    float xv[7];
#pragma unroll
    for (int j = 0; j < 7; ++j) {
        int tt = t0 - 3 + j;
        xv[j] = (tt >= 0) ? qkvz[(size_t)tt * QKVZ_N + c] : 0.0f;
    }
#pragma unroll
    for (int i = 0; i < 4; ++i) {
        float a = w[0] * xv[i];
        a = fmaf(w[1], xv[i + 1], a);
        a = fmaf(w[2], xv[i + 2], a);
        a = fmaf(w[3], xv[i + 3], a);
        out[(size_t)(t0 + i) * CONV_DIM + c] = siluf_(a);
    }
}

// ---------------- gating ----------------
__global__ __launch_bounds__(256) void gate_prep(
    const float* __restrict__ ba, const float* __restrict__ A_log,
    const float* __restrict__ dt_bias, float2* __restrict__ egbeta)
{
    int i = blockIdx.x * blockDim.x + threadIdx.x;
    if (i >= T_SEQ * NUM_V) return;
    int t = i >> 5;
    int h = i & 31;
    float b = ba[(size_t)t * 64 + h];
    float a = ba[(size_t)t * 64 + 32 + h];
    float x = a + dt_bias[h];
    float sp = (x > 20.0f) ? x : log1pf(expf(x));
    float g = -expf(A_log[h]) * sp;
    egbeta[i] = make_float2(expf(g), sigmoidf_(b));
}

// ---------------- fused l2norm(q,k) + qk dot: one warp per (t, key-head) ----------------
__global__ __launch_bounds__(256) void l2norm_qk_dot(
    const float* __restrict__ qkv, float* __restrict__ qhat,
    float* __restrict__ khat, float* __restrict__ qkdot)
{
    int gid  = blockIdx.x * 8 + (threadIdx.x >> 5);
    int lane = threadIdx.x & 31;
    int t  = gid >> 4;
    int kh = gid & 15;
    const float* qsrc = qkv + (size_t)t * CONV_DIM + kh * DK;
    float4 q = *((const float4*)qsrc + lane);
    float4 k = *((const float4*)(qsrc + KEY_DIM) + lane);
    float sq  = q.x * q.x + q.y * q.y + q.z * q.z + q.w * q.w;
    float sk  = k.x * k.x + k.y * k.y + k.z * k.z + k.w * k.w;
    float sqk = q.x * k.x + q.y * k.y + q.z * k.z + q.w * k.w;
#pragma unroll
    for (int off = 16; off > 0; off >>= 1) {
        sq  += __shfl_xor_sync(0xffffffffu, sq,  off);
        sk  += __shfl_xor_sync(0xffffffffu, sk,  off);
        sqk += __shfl_xor_sync(0xffffffffu, sqk, off);
    }
    float rq = rsqrtf(sq + 1e-6f) * QSCALE;
    float rk = rsqrtf(sk + 1e-6f);
    size_t base = (size_t)t * KEY_DIM + kh * DK;
    *((float4*)(qhat + base) + lane) = make_float4(q.x * rq, q.y * rq, q.z * rq, q.w * rq);
    *((float4*)(khat + base) + lane) = make_float4(k.x * rk, k.y * rk, k.z * rk, k.w * rk);
    if (lane == 0) qkdot[t * NUM_K + kh] = sqk * rq * rk;
}

// ---------------- gated delta scan: smem-staged, double-buffered ----------------
// CTA = (head, 16-col group); 8 warps x 2 cols; chunks of 32 timesteps via cp.async.
// smem per buffer (bytes): K 16384 | Q 16384 | V 2048 | EB 256 | XQ 128 -> pad 35328
#define SC_TC   32
#define SC_QB   16384
#define SC_VB   32768
#define SC_EB   34816
#define SC_XB   35072
#define SC_BUF  35328
#define SC_SMEM (2 * SC_BUF)

__device__ __forceinline__ void scan_stage(
    uint32_t sbase, const float* kb_, const float* qb_,
    const float* vb_, const float* eb_, const float* xb_, int tid)
{
    // k/q: j = 0..31 float4s per row; store even j at [0,256)B, odd j at [256,512)B
#pragma unroll
    for (int i = 0; i < 8; ++i) {
        int idx = tid + i * 256;          // 0..2047
        int isq = idx >> 10;
        int r   = idx & 1023;
        int tt  = r >> 5;
        int j   = r & 31;
        const float* src = (isq ? qb_ : kb_) + (size_t)tt * KEY_DIM + j * 4;
        uint32_t dst = sbase + (isq ? SC_QB : 0) + tt * 512 + ((j & 1) << 8) + ((j >> 1) << 4);
        asm volatile("cp.async.ca.shared.global [%0], [%1], 16;" :: "r"(dst), "l"(src));
    }
    if (tid < 128) {                      // v: 16 floats per tt = 4 float4
        int tt = tid >> 2, j = tid & 3;
        const float* src = vb_ + (size_t)tt * CONV_DIM + j * 4;
        uint32_t dst = sbase + SC_VB + tt * 64 + j * 16;
        asm volatile("cp.async.ca.shared.global [%0], [%1], 16;" :: "r"(dst), "l"(src));
    } else if (tid < 160) {               // egbeta: float2 per tt
        int tt = tid - 128;
        const float* src = eb_ + (size_t)tt * (2 * NUM_V);
        uint32_t dst = sbase + SC_EB + tt * 8;
        asm volatile("cp.async.ca.shared.global [%0], [%1], 8;" :: "r"(dst), "l"(src));
    } else if (tid < 192) {               // qkdot: float per tt
        int tt = tid - 160;
        const float* src = xb_ + (size_t)tt * NUM_K;
        uint32_t dst = sbase + SC_XB + tt * 4;
        asm volatile("cp.async.ca.shared.global [%0], [%1], 4;" :: "r"(dst), "l"(src));
    }
}

__global__ __launch_bounds__(256) void gdn_scan(
    const float* __restrict__ qhat, const float* __restrict__ khat,
    const float* __restrict__ qkv, const float* __restrict__ egbeta,
    const float* __restrict__ qk, float* __restrict__ o)
{
    extern __shared__ __align__(128) char ssm[];
    const uint32_t sbase = smem_to_u32(ssm);
    const float* sf = (const float*)ssm;

    const int tid  = threadIdx.x;
    const int warp = tid >> 5;
    const int lane = tid & 31;
    const int half = lane >> 4;
    const int sl   = lane & 15;
    const int h    = blockIdx.x >> 3;
    const int cb   = (blockIdx.x & 7) * 16;     // column base
    const int col  = cb + warp * 2 + half;
    const int kh   = h >> 1;

    const float* kb_ = khat + kh * DK;
    const float* qb_ = qhat + kh * DK;
    const float* vb_ = qkv + 2 * KEY_DIM + h * DV + cb;
    const float* eb_ = egbeta + 2 * h;
    const float* xb_ = qk + kh;
    float*       op  = o + h * DV + col;

    const int NC = T_SEQ / SC_TC;                // 64

    float4 Sa = make_float4(0.f, 0.f, 0.f, 0.f);
    float4 Sb = make_float4(0.f, 0.f, 0.f, 0.f);

    scan_stage(sbase, kb_, qb_, vb_, eb_, xb_, tid);
    asm volatile("cp.async.commit_group;");

    for (int c = 0; c < NC; ++c) {
        if (c + 1 < NC) {
            size_t adv = (size_t)(c + 1) * SC_TC;
            scan_stage(sbase + ((c + 1) & 1) * SC_BUF,
                       kb_ + adv * KEY_DIM, qb_ + adv * KEY_DIM,
                       vb_ + adv * CONV_DIM, eb_ + adv * 2 * NUM_V,
                       xb_ + adv * NUM_K, tid);
            asm volatile("cp.async.commit_group;");
            asm volatile("cp.async.wait_group 1;");
        } else {
            asm volatile("cp.async.wait_group 0;");
        }
        __syncthreads();

        const int bo = (c & 1) * (SC_BUF / 4);   // float offset of buffer
        for (int tt = 0; tt < SC_TC; ++tt) {
            const float* kr = sf + bo + tt * 128;
            const float* qr = sf + bo + SC_QB / 4 + tt * 128;
            float4 k0 = *(const float4*)(kr + sl * 4);
            float4 k1 = *(const float4*)(kr + 64 + sl * 4);
            float4 q0 = *(const float4*)(qr + sl * 4);
            float4 q1 = *(const float4*)(qr + 64 + sl * 4);
            float  vt = sf[bo + SC_VB / 4 + tt * 16 + warp * 2 + half];
            float  eg = sf[bo + SC_EB / 4 + tt * 2];
            float  bt = sf[bo + SC_EB / 4 + tt * 2 + 1];
            float  xq = sf[bo + SC_XB / 4 + tt];

            float dk = k0.x * Sa.x + k0.y * Sa.y + k0.z * Sa.z + k0.w * Sa.w
                     + k1.x * Sb.x + k1.y * Sb.y + k1.z * Sb.z + k1.w * Sb.w;
            float dq = q0.x * Sa.x + q0.y * Sa.y + q0.z * Sa.z + q0.w * Sa.w
                     + q1.x * Sb.x + q1.y * Sb.y + q1.z * Sb.z + q1.w * Sb.w;
#pragma unroll
            for (int off = 8; off > 0; off >>= 1) {
                dk += __shfl_xor_sync(0xffffffffu, dk, off);
                dq += __shfl_xor_sync(0xffffffffu, dq, off);
            }
            const float delta = (vt - eg * dk) * bt;
            const float ot    = fmaf(eg, dq, xq * delta);
            Sa.x = fmaf(Sa.x, eg, k0.x * delta);
            Sa.y = fmaf(Sa.y, eg, k0.y * delta);
            Sa.z = fmaf(Sa.z, eg, k0.z * delta);
            Sa.w = fmaf(Sa.w, eg, k0.w * delta);
            Sb.x = fmaf(Sb.x, eg, k1.x * delta);
            Sb.y = fmaf(Sb.y, eg, k1.y * delta);
            Sb.z = fmaf(Sb.z, eg, k1.z * delta);
            Sb.w = fmaf(Sb.w, eg, k1.w * delta);
            if (sl == 0) op[(size_t)(c * SC_TC + tt) * VAL_DIM] = ot;
        }
        __syncthreads();
    }
}

// ---------------- RMSNorm * norm_w * silu(z), write fp16 hi/lo directly ----------------
__global__ __launch_bounds__(256) void rms_gate_split(
    const float* __restrict__ o, const float* __restrict__ qkvz,
    const float* __restrict__ norm_w,
    __half* __restrict__ hi, __half* __restrict__ lo)
{
    int gid  = blockIdx.x * 8 + (threadIdx.x >> 5);
    int lane = threadIdx.x & 31;
    int t = gid >> 5;
    int h = gid & 31;
    const float* orow = o + (size_t)t * VAL_DIM + h * DV;
    float4 x = *(const float4*)(orow + lane * 4);
    float s = x.x * x.x + x.y * x.y + x.z * x.z + x.w * x.w;
#pragma unroll
    for (int off = 16; off > 0; off >>= 1) s += __shfl_xor_sync(0xffffffffu, s, off);
    float r = rsqrtf(s * (1.0f / DV) + 1e-6f);
    float4 z  = *(const float4*)(qkvz + (size_t)t * QKVZ_N + 2 * KEY_DIM + VAL_DIM + h * DV + lane * 4);
    float4 nw = *(const float4*)(norm_w + lane * 4);
    float4 y;
    y.x = x.x * r * nw.x * siluf_(z.x);
    y.y = x.y * r * nw.y * siluf_(z.y);
    y.z = x.z * r * nw.z * siluf_(z.z);
    y.w = x.w * r * nw.w * siluf_(z.w);
    __half h0 = __float2half_rn(y.x), h1 = __float2half_rn(y.y);
    __half h2 = __float2half_rn(y.z), h3 = __float2half_rn(y.w);
    __half l0 = __float2half_rn(y.x - __half2float(h0));
    __half l1 = __float2half_rn(y.y - __half2float(h1));
    __half l2 = __float2half_rn(y.z - __half2float(h2));
    __half l3 = __float2half_rn(y.w - __half2float(h3));
    union { __half2 h2v[2]; uint2 u; } H, L;
    H.h2v[0] = __halves2half2(h0, h1); H.h2v[1] = __halves2half2(h2, h3);
    L.h2v[0] = __halves2half2(l0, l1); L.h2v[1] = __halves2half2(l2, l3);
    int i4 = (t * VAL_DIM + h * DV) / 4 + lane;
    ((uint2*)hi)[i4] = H.u;
    ((uint2*)lo)[i4] = L.u;
}

// ---------------- launch ----------------
extern "C" void kernel_launch(void* const* d_in, const int* in_sizes, int n_in,
                              void* d_out, int out_size)
{
    const float* h_in    = (const float*)d_in[0];
    const float* W_qkvz  = (const float*)d_in[1];
    const float* W_ba    = (const float*)d_in[2];
    const float* conv_w  = (const float*)d_in[3];
    const float* dt_bias = (const float*)d_in[4];
    const float* A_log   = (const float*)d_in[5];
    const float* norm_w  = (const float*)d_in[6];
    const float* W_out   = (const float*)d_in[7];
    float* out = (float*)d_out;

    float *qkvz, *qkv, *ba, *qhat, *khat, *qkdot, *oscan;
    float2* egbeta;
    __half *Wq, *Wo, *A_hi, *A_lo;
    cudaGetSymbolAddress((void**)&qkvz,   g_qkvz);
    cudaGetSymbolAddress((void**)&qkv,    g_qkv);
    cudaGetSymbolAddress((void**)&ba,     g_ba);
    cudaGetSymbolAddress((void**)&egbeta, g_egbeta);
    cudaGetSymbolAddress((void**)&qhat,   g_qhat);
    cudaGetSymbolAddress((void**)&khat,   g_khat);
    cudaGetSymbolAddress((void**)&qkdot,  g_qkdot);
    cudaGetSymbolAddress((void**)&oscan,  g_oscan);
    cudaGetSymbolAddress((void**)&Wq,     g_Wq);
    cudaGetSymbolAddress((void**)&Wo,     g_Wo);
    cudaGetSymbolAddress((void**)&A_hi,   g_A_hi);
    cudaGetSymbolAddress((void**)&A_lo,   g_A_lo);

    cudaFuncSetAttribute(gemm_tc, cudaFuncAttributeMaxDynamicSharedMemorySize, GT_SMEM);
    cudaFuncSetAttribute(gdn_scan, cudaFuncAttributeMaxDynamicSharedMemorySize, SC_SMEM);

    // prep
    {
        dim3 blk(32, 8);
        tr_half<<<dim3(QKVZ_N / 32, HID / 32), blk>>>(W_qkvz, Wq, HID, QKVZ_N);
        tr_half<<<dim3(HID / 32, VAL_DIM / 32), blk>>>(W_out, Wo, VAL_DIM, HID);
    }
    cvt_split<<<(T_SEQ * HID / 4 + 255) / 256, 256>>>(h_in, A_hi, A_lo, T_SEQ * HID / 4);

    // GEMM1: qkvz = h @ W_qkvz   [2048 x 12288], K=2048
    gemm_tc<<<dim3(T_SEQ / 128, QKVZ_N / 256), 512, GT_SMEM>>>(A_hi, A_lo, Wq, qkvz, QKVZ_N, HID);

    gemm_ba<<<T_SEQ / 64, 256>>>(h_in, W_ba, ba);
    conv_silu<<<((T_SEQ / 4) * CONV_DIM) / 256, 256>>>(qkvz, conv_w, qkv);
    gate_prep<<<(T_SEQ * NUM_V) / 256, 256>>>(ba, A_log, dt_bias, egbeta);
    l2norm_qk_dot<<<(T_SEQ * NUM_K) / 8, 256>>>(qkv, qhat, khat, qkdot);
    gdn_scan<<<NUM_V * 8, 256, SC_SMEM>>>(qhat, khat, qkv, (const float*)egbeta, qkdot, oscan);
    rms_gate_split<<<(T_SEQ * NUM_V) / 8, 256>>>(oscan, qkvz, norm_w, A_hi, A_lo);

    // GEMM2: out = gated @ W_out  [2048 x 2048], K=4096
    gemm_tc<<<dim3(T_SEQ / 128, HID / 256), 512, GT_SMEM>>>(A_hi, A_lo, Wo, out, HID, VAL_DIM);
}

// round 13
// speedup vs baseline: 1.6178x; 1.0844x over previous
#include <cuda_runtime.h>
#include <cuda_fp16.h>
#include <math.h>
#include <stdint.h>

// ---------------- problem constants ----------------
#define T_SEQ   2048
#define HID     2048
#define NUM_K   16
#define NUM_V   32
#define DK      128
#define DV      128
#define KEY_DIM 2048
#define VAL_DIM 4096
#define CONV_DIM 8192
#define QKVZ_N  12288
#define QSCALE  0.08838834764831845f

// ---------------- scratch ----------------
__device__ float  g_qkvz  [T_SEQ * QKVZ_N];
__device__ float  g_qkv   [T_SEQ * CONV_DIM];
__device__ float  g_ba    [T_SEQ * 64];
__device__ float2 g_egbeta[T_SEQ * NUM_V];
__device__ float  g_qhat  [T_SEQ * KEY_DIM];
__device__ float  g_khat  [T_SEQ * KEY_DIM];
__device__ float  g_qkdot [T_SEQ * NUM_K];
__device__ float  g_oscan [T_SEQ * VAL_DIM];

// fp16 operands: weights single fp16 (W^T), activations split hi/lo
__device__ __half g_Wq[QKVZ_N * HID];
__device__ __half g_Wo[HID * VAL_DIM];
__device__ __half g_A_hi[T_SEQ * VAL_DIM];
__device__ __half g_A_lo[T_SEQ * VAL_DIM];

// ---------------- helpers ----------------
__device__ __forceinline__ float sigmoidf_(float x) { return 1.0f / (1.0f + __expf(-x)); }
__device__ __forceinline__ float siluf_(float x)    { return x * sigmoidf_(x); }

__device__ __forceinline__ uint32_t smem_to_u32(const void* p) {
    uint32_t a;
    asm("{ .reg .u64 t; cvta.to.shared.u64 t, %1; cvt.u32.u64 %0, t; }" : "=r"(a) : "l"(p));
    return a;
}
__device__ __forceinline__ void ldsm4(uint32_t& r0, uint32_t& r1, uint32_t& r2, uint32_t& r3,
                                      uint32_t addr) {
    asm volatile("ldmatrix.sync.aligned.m8n8.x4.shared.b16 {%0,%1,%2,%3}, [%4];"
                 : "=r"(r0), "=r"(r1), "=r"(r2), "=r"(r3) : "r"(addr));
}
__device__ __forceinline__ void mma16816(float* d, const uint32_t* a, const uint32_t* b) {
    asm volatile("mma.sync.aligned.m16n8k16.row.col.f32.f16.f16.f32 "
                 "{%0,%1,%2,%3}, {%4,%5,%6,%7}, {%8,%9}, {%0,%1,%2,%3};"
                 : "+f"(d[0]), "+f"(d[1]), "+f"(d[2]), "+f"(d[3])
                 : "r"(a[0]), "r"(a[1]), "r"(a[2]), "r"(a[3]), "r"(b[0]), "r"(b[1]));
}

// ---------------- prep: fp32 -> fp16 hi/lo split ----------------
__global__ __launch_bounds__(256) void cvt_split(
    const float* __restrict__ x, __half* __restrict__ hi,
    __half* __restrict__ lo, int n4)
{
    int i = blockIdx.x * 256 + threadIdx.x;
    if (i >= n4) return;
    float4 v = ((const float4*)x)[i];
    __half h0 = __float2half_rn(v.x), h1 = __float2half_rn(v.y);
    __half h2 = __float2half_rn(v.z), h3 = __float2half_rn(v.w);
    __half l0 = __float2half_rn(v.x - __half2float(h0));
    __half l1 = __float2half_rn(v.y - __half2float(h1));
    __half l2 = __float2half_rn(v.z - __half2float(h2));
    __half l3 = __float2half_rn(v.w - __half2float(h3));
    union { __half2 h2v[2]; uint2 u; } H, L;
    H.h2v[0] = __halves2half2(h0, h1); H.h2v[1] = __halves2half2(h2, h3);
    L.h2v[0] = __halves2half2(l0, l1); L.h2v[1] = __halves2half2(l2, l3);
    ((uint2*)hi)[i] = H.u;
    ((uint2*)lo)[i] = L.u;
}

// ---------------- prep: W [K][N] fp32 -> W^T [N][K] fp16 ----------------
__global__ __launch_bounds__(256) void tr_half(
    const float* __restrict__ W, __half* __restrict__ out, int K, int N)
{
    __shared__ float t[32][33];
    int n0 = blockIdx.x * 32, k0 = blockIdx.y * 32;
    int tx = threadIdx.x, ty = threadIdx.y;
#pragma unroll
    for (int j = 0; j < 4; ++j)
        t[ty + j * 8][tx] = W[(size_t)(k0 + ty + j * 8) * N + n0 + tx];
    __syncthreads();
#pragma unroll
    for (int j = 0; j < 4; ++j) {
        int n = ty + j * 8;
        out[(size_t)(n0 + n) * K + k0 + tx] = __float2half_rn(t[tx][n]);
    }
}

// ---------------- mma.sync GEMM: 128x128 CTA, 256 threads, BK=64, 2-stage, 2 CTA/SM ----------------
#define SSTR   144
#define SZ_A   (128 * SSTR)              // 18432
#define SZ_B   (128 * SSTR)              // 18432
#define BUF_SZ (2 * SZ_A + SZ_B)         // 55296
#define GT_SMEM (2 * BUF_SZ)             // 110592

template<int ITERS>
__device__ __forceinline__ void cpa_stage(uint32_t sdst, const char* g, int Kb, int tid) {
#pragma unroll
    for (int i = 0; i < ITERS; ++i) {
        int idx = tid + i * 256;
        int row = idx >> 3;
        int q   = (idx & 7) << 4;
        uint32_t d = sdst + row * SSTR + q;
        const char* s = g + (size_t)row * Kb + q;
        asm volatile("cp.async.cg.shared.global [%0], [%1], 16;" :: "r"(d), "l"(s));
    }
}

template<int USE_LO>
__global__ __launch_bounds__(256, 2) void gemm_tc(
    const __half* __restrict__ Ahi, const __half* __restrict__ Alo,
    const __half* __restrict__ B, float* __restrict__ C, int N, int K)
{
    extern __shared__ __align__(128) char smem[];
    const uint32_t sb = smem_to_u32(smem);

    const int tid  = threadIdx.x;
    const int wid  = tid >> 5;
    const int lane = tid & 31;
    const int bm   = blockIdx.x * 128;
    const int bn   = blockIdx.y * 128;
    const int wm   = (wid >> 1) * 32;    // 4 warp-rows of 32
    const int wn   = (wid & 1) * 64;     // 2 warp-cols of 64
    const int Kb   = K * 2;

    const char* gAh = (const char*)(Ahi + (size_t)bm * K);
    const char* gAl = (const char*)(Alo + (size_t)bm * K);
    const char* gB  = (const char*)(B   + (size_t)bn * K);

    float acc[2][8][4];
#pragma unroll
    for (int i = 0; i < 2; ++i)
#pragma unroll
        for (int j = 0; j < 8; ++j)
#pragma unroll
            for (int r = 0; r < 4; ++r) acc[i][j][r] = 0.0f;

    const uint32_t aoff = (lane & 15) * SSTR + ((lane >> 4) << 4);
    const uint32_t boff = ((lane & 7) + ((lane >> 4) << 3)) * SSTR + (((lane >> 3) & 1) << 4);

    const int nk = K >> 6;

    {
        uint32_t sbuf = sb;
        cpa_stage<4>(sbuf,            gAh, Kb, tid);
        if (USE_LO) cpa_stage<4>(sbuf + SZ_A, gAl, Kb, tid);
        cpa_stage<4>(sbuf + 2 * SZ_A, gB,  Kb, tid);
        asm volatile("cp.async.commit_group;");
    }

    for (int kt = 0; kt < nk; ++kt) {
        asm volatile("cp.async.wait_group 0;");
        __syncthreads();

        if (kt + 1 < nk) {
            uint32_t sbuf = sb + ((kt + 1) & 1) * BUF_SZ;
            size_t ko = (size_t)(kt + 1) * 128;
            cpa_stage<4>(sbuf,            gAh + ko, Kb, tid);
            if (USE_LO) cpa_stage<4>(sbuf + SZ_A, gAl + ko, Kb, tid);
            cpa_stage<4>(sbuf + 2 * SZ_A, gB  + ko, Kb, tid);
            asm volatile("cp.async.commit_group;");
        }

        const uint32_t sAh = sb + (kt & 1) * BUF_SZ;
        const uint32_t sAl = sAh + SZ_A;
        const uint32_t sB  = sAh + 2 * SZ_A;

#pragma unroll
        for (int ks = 0; ks < 4; ++ks) {
            const uint32_t kb = ks * 32;
            uint32_t ah[2][4], al[2][4];
#pragma unroll
            for (int mt = 0; mt < 2; ++mt) {
                uint32_t base = (wm + mt * 16) * SSTR + aoff + kb;
                ldsm4(ah[mt][0], ah[mt][1], ah[mt][2], ah[mt][3], sAh + base);
                if (USE_LO)
                    ldsm4(al[mt][0], al[mt][1], al[mt][2], al[mt][3], sAl + base);
            }
#pragma unroll
            for (int pr = 0; pr < 4; ++pr) {
                uint32_t bbase = (wn + pr * 16) * SSTR + boff + kb;
                uint32_t h0, h1, h2, h3;
                ldsm4(h0, h1, h2, h3, sB + bbase);
                uint32_t b0[2] = {h0, h1}, b1[2] = {h2, h3};
#pragma unroll
                for (int mt = 0; mt < 2; ++mt) {
                    mma16816(acc[mt][2 * pr],     ah[mt], b0);
                    mma16816(acc[mt][2 * pr + 1], ah[mt], b1);
                    if (USE_LO) {
                        mma16816(acc[mt][2 * pr],     al[mt], b0);
                        mma16816(acc[mt][2 * pr + 1], al[mt], b1);
                    }
                }
            }
        }
    }

    const int g  = lane >> 2;
    const int tg = lane & 3;
#pragma unroll
    for (int mt = 0; mt < 2; ++mt) {
#pragma unroll
        for (int nt = 0; nt < 8; ++nt) {
            const float* d = acc[mt][nt];
            size_t r = (size_t)(bm + wm + mt * 16 + g) * N + bn + wn + nt * 8 + tg * 2;
            *(float2*)&C[r] = make_float2(d[0], d[1]);
            *(float2*)&C[r + 8 * (size_t)N] = make_float2(d[2], d[3]);
        }
    }
}

// ---------------- tiled small GEMM: ba = h @ W_ba (2048x64, K=2048) ----------------
__global__ __launch_bounds__(256) void gemm_ba(
    const float* __restrict__ A, const float* __restrict__ B, float* __restrict__ C)
{
    __shared__ float sh[64][65];
    __shared__ float sB[64][65];
    const int tid = threadIdx.x;
    const int col = tid & 63;
    const int rg  = tid >> 6;
    const int br  = blockIdx.x * 64;

    float acc[16];
#pragma unroll
    for (int r = 0; r < 16; ++r) acc[r] = 0.0f;

    for (int kt = 0; kt < HID / 64; ++kt) {
#pragma unroll
        for (int i = 0; i < 16; ++i) {
            int idx = tid + i * 256;
            int row = idx >> 6, kk = idx & 63;
            sh[row][kk] = A[(size_t)(br + row) * HID + kt * 64 + kk];
            sB[row][kk] = B[(size_t)(kt * 64 + row) * 64 + kk];
        }
        __syncthreads();
#pragma unroll 16
        for (int kk = 0; kk < 64; ++kk) {
            float b = sB[kk][col];
#pragma unroll
            for (int r = 0; r < 16; ++r)
                acc[r] = fmaf(sh[rg * 16 + r][kk], b, acc[r]);
        }
        __syncthreads();
    }
#pragma unroll
    for (int r = 0; r < 16; ++r)
        C[(size_t)(br + rg * 16 + r) * 64 + col] = acc[r];
}

// ---------------- causal depthwise conv (K=4) + SiLU, 4 t per thread ----------------
__global__ __launch_bounds__(256) void conv_silu(
    const float* __restrict__ qkvz, const float* __restrict__ conv_w,
    float* __restrict__ out)
{
    int idx = blockIdx.x * blockDim.x + threadIdx.x;
    if (idx >= (T_SEQ / 4) * CONV_DIM) return;
    int tq = idx >> 13;
    int c  = idx & (CONV_DIM - 1);
    int t0 = tq * 4;
    const float* w = conv_w + c * 4;
    float xv[7];
#pragma unroll
    for (int j = 0; j < 7; ++j) {
        int tt = t0 - 3 + j;
        xv[j] = (tt >= 0) ? qkvz[(size_t)tt * QKVZ_N + c] : 0.0f;
    }
#pragma unroll
    for (int i = 0; i < 4; ++i) {
        float a = w[0] * xv[i];
        a = fmaf(w[1], xv[i + 1], a);
        a = fmaf(w[2], xv[i + 2], a);
        a = fmaf(w[3], xv[i + 3], a);
        out[(size_t)(t0 + i) * CONV_DIM + c] = siluf_(a);
    }
}

// ---------------- gating ----------------
__global__ __launch_bounds__(256) void gate_prep(
    const float* __restrict__ ba, const float* __restrict__ A_log,
    const float* __restrict__ dt_bias, float2* __restrict__ egbeta)
{
    int i = blockIdx.x * blockDim.x + threadIdx.x;
    if (i >= T_SEQ * NUM_V) return;
    int t = i >> 5;
    int h = i & 31;
    float b = ba[(size_t)t * 64 + h];
    float a = ba[(size_t)t * 64 + 32 + h];
    float x = a + dt_bias[h];
    float sp = (x > 20.0f) ? x : log1pf(expf(x));
    float g = -expf(A_log[h]) * sp;
    egbeta[i] = make_float2(expf(g), sigmoidf_(b));
}

// ---------------- fused l2norm(q,k) + qk dot: one warp per (t, key-head) ----------------
__global__ __launch_bounds__(256) void l2norm_qk_dot(
    const float* __restrict__ qkv, float* __restrict__ qhat,
    float* __restrict__ khat, float* __restrict__ qkdot)
{
    int gid  = blockIdx.x * 8 + (threadIdx.x >> 5);
    int lane = threadIdx.x & 31;
    int t  = gid >> 4;
    int kh = gid & 15;
    const float* qsrc = qkv + (size_t)t * CONV_DIM + kh * DK;
    float4 q = *((const float4*)qsrc + lane);
    float4 k = *((const float4*)(qsrc + KEY_DIM) + lane);
    float sq  = q.x * q.x + q.y * q.y + q.z * q.z + q.w * q.w;
    float sk  = k.x * k.x + k.y * k.y + k.z * k.z + k.w * k.w;
    float sqk = q.x * k.x + q.y * k.y + q.z * k.z + q.w * k.w;
#pragma unroll
    for (int off = 16; off > 0; off >>= 1) {
        sq  += __shfl_xor_sync(0xffffffffu, sq,  off);
        sk  += __shfl_xor_sync(0xffffffffu, sk,  off);
        sqk += __shfl_xor_sync(0xffffffffu, sqk, off);
    }
    float rq = rsqrtf(sq + 1e-6f) * QSCALE;
    float rk = rsqrtf(sk + 1e-6f);
    size_t base = (size_t)t * KEY_DIM + kh * DK;
    *((float4*)(qhat + base) + lane) = make_float4(q.x * rq, q.y * rq, q.z * rq, q.w * rq);
    *((float4*)(khat + base) + lane) = make_float4(k.x * rk, k.y * rk, k.z * rk, k.w * rk);
    if (lane == 0) qkdot[t * NUM_K + kh] = sqk * rq * rk;
}

// ---------------- gated delta scan: smem-staged, double-buffered, 16 warps/CTA ----------------
// CTA = (head, 32-col group); 16 warps x 2 cols; chunks of 32 timesteps via cp.async.
// smem per buffer (bytes): K 16384 | Q 16384 | V 4096 | EB 256 | XQ 128 -> pad 37376
#define SC_TC   32
#define SC_QB   16384
#define SC_VB   32768
#define SC_EB   36864
#define SC_XB   37120
#define SC_BUF  37376
#define SC_SMEM (2 * SC_BUF)

__device__ __forceinline__ void scan_stage(
    uint32_t sbase, const float* kb_, const float* qb_,
    const float* vb_, const float* eb_, const float* xb_, int tid)
{
    // k/q: j = 0..31 float4s per row; store even j at [0,256)B, odd j at [256,512)B
#pragma unroll
    for (int i = 0; i < 4; ++i) {
        int idx = tid + i * 512;          // 0..2047
        int isq = idx >> 10;
        int r   = idx & 1023;
        int tt  = r >> 5;
        int j   = r & 31;
        const float* src = (isq ? qb_ : kb_) + (size_t)tt * KEY_DIM + j * 4;
        uint32_t dst = sbase + (isq ? SC_QB : 0) + tt * 512 + ((j & 1) << 8) + ((j >> 1) << 4);
        asm volatile("cp.async.ca.shared.global [%0], [%1], 16;" :: "r"(dst), "l"(src));
    }
    if (tid < 256) {                      // v: 32 floats per tt = 8 float4
        int tt = tid >> 3, j = tid & 7;
        const float* src = vb_ + (size_t)tt * CONV_DIM + j * 4;
        uint32_t dst = sbase + SC_VB + tt * 128 + j * 16;
        asm volatile("cp.async.ca.shared.global [%0], [%1], 16;" :: "r"(dst), "l"(src));
    } else if (tid < 288) {               // egbeta: float2 per tt
        int tt = tid - 256;
        const float* src = eb_ + (size_t)tt * (2 * NUM_V);
        uint32_t dst = sbase + SC_EB + tt * 8;
        asm volatile("cp.async.ca.shared.global [%0], [%1], 8;" :: "r"(dst), "l"(src));
    } else if (tid < 320) {               // qkdot: float per tt
        int tt = tid - 288;
        const float* src = xb_ + (size_t)tt * NUM_K;
        uint32_t dst = sbase + SC_XB + tt * 4;
        asm volatile("cp.async.ca.shared.global [%0], [%1], 4;" :: "r"(dst), "l"(src));
    }
}

__global__ __launch_bounds__(512) void gdn_scan(
    const float* __restrict__ qhat, const float* __restrict__ khat,
    const float* __restrict__ qkv, const float* __restrict__ egbeta,
    const float* __restrict__ qk, float* __restrict__ o)
{
    extern __shared__ __align__(128) char ssm[];
    const uint32_t sbase = smem_to_u32(ssm);
    const float* sf = (const float*)ssm;

    const int tid  = threadIdx.x;
    const int warp = tid >> 5;                  // 0..15
    const int lane = tid & 31;
    const int half = lane >> 4;
    const int sl   = lane & 15;
    const int h    = blockIdx.x >> 2;           // 32 heads x 4 groups
    const int cb   = (blockIdx.x & 3) * 32;     // column base
    const int col  = cb + warp * 2 + half;
    const int kh   = h >> 1;

    const float* kb_ = khat + kh * DK;
    const float* qb_ = qhat + kh * DK;
    const float* vb_ = qkv + 2 * KEY_DIM + h * DV + cb;
    const float* eb_ = egbeta + 2 * h;
    const float* xb_ = qk + kh;
    float*       op  = o + h * DV + col;

    const int NC = T_SEQ / SC_TC;                // 64

    float4 Sa = make_float4(0.f, 0.f, 0.f, 0.f);
    float4 Sb = make_float4(0.f, 0.f, 0.f, 0.f);

    scan_stage(sbase, kb_, qb_, vb_, eb_, xb_, tid);
    asm volatile("cp.async.commit_group;");

    for (int c = 0; c < NC; ++c) {
        if (c + 1 < NC) {
            size_t adv = (size_t)(c + 1) * SC_TC;
            scan_stage(sbase + ((c + 1) & 1) * SC_BUF,
                       kb_ + adv * KEY_DIM, qb_ + adv * KEY_DIM,
                       vb_ + adv * CONV_DIM, eb_ + adv * 2 * NUM_V,
                       xb_ + adv * NUM_K, tid);
            asm volatile("cp.async.commit_group;");
            asm volatile("cp.async.wait_group 1;");
        } else {
            asm volatile("cp.async.wait_group 0;");
        }
        __syncthreads();

        const int bo = (c & 1) * (SC_BUF / 4);
        for (int tt = 0; tt < SC_TC; ++tt) {
            const float* kr = sf + bo + tt * 128;
            const float* qr = sf + bo + SC_QB / 4 + tt * 128;
            float4 k0 = *(const float4*)(kr + sl * 4);
            float4 k1 = *(const float4*)(kr + 64 + sl * 4);
            float4 q0 = *(const float4*)(qr + sl * 4);
            float4 q1 = *(const float4*)(qr + 64 + sl * 4);
            float  vt = sf[bo + SC_VB / 4 + tt * 32 + warp * 2 + half];
            float  eg = sf[bo + SC_EB / 4 + tt * 2];
            float  bt = sf[bo + SC_EB / 4 + tt * 2 + 1];
            float  xq = sf[bo + SC_XB / 4 + tt];

            float dk = k0.x * Sa.x + k0.y * Sa.y + k0.z * Sa.z + k0.w * Sa.w
                     + k1.x * Sb.x + k1.y * Sb.y + k1.z * Sb.z + k1.w * Sb.w;
            float dq = q0.x * Sa.x + q0.y * Sa.y + q0.z * Sa.z + q0.w * Sa.w
                     + q1.x * Sb.x + q1.y * Sb.y + q1.z * Sb.z + q1.w * Sb.w;
#pragma unroll
            for (int off = 8; off > 0; off >>= 1) {
                dk += __shfl_xor_sync(0xffffffffu, dk, off);
                dq += __shfl_xor_sync(0xffffffffu, dq, off);
            }
            const float delta = (vt - eg * dk) * bt;
            const float ot    = fmaf(eg, dq, xq * delta);
            Sa.x = fmaf(Sa.x, eg, k0.x * delta);
            Sa.y = fmaf(Sa.y, eg, k0.y * delta);
            Sa.z = fmaf(Sa.z, eg, k0.z * delta);
            Sa.w = fmaf(Sa.w, eg, k0.w * delta);
            Sb.x = fmaf(Sb.x, eg, k1.x * delta);
            Sb.y = fmaf(Sb.y, eg, k1.y * delta);
            Sb.z = fmaf(Sb.z, eg, k1.z * delta);
            Sb.w = fmaf(Sb.w, eg, k1.w * delta);
            if (sl == 0) op[(size_t)(c * SC_TC + tt) * VAL_DIM] = ot;
        }
        __syncthreads();
    }
}

// ---------------- RMSNorm * norm_w * silu(z), write fp16 hi/lo directly ----------------
__global__ __launch_bounds__(256) void rms_gate_split(
    const float* __restrict__ o, const float* __restrict__ qkvz,
    const float* __restrict__ norm_w,
    __half* __restrict__ hi, __half* __restrict__ lo)
{
    int gid  = blockIdx.x * 8 + (threadIdx.x >> 5);
    int lane = threadIdx.x & 31;
    int t = gid >> 5;
    int h = gid & 31;
    const float* orow = o + (size_t)t * VAL_DIM + h * DV;
    float4 x = *(const float4*)(orow + lane * 4);
    float s = x.x * x.x + x.y * x.y + x.z * x.z + x.w * x.w;
#pragma unroll
    for (int off = 16; off > 0; off >>= 1) s += __shfl_xor_sync(0xffffffffu, s, off);
    float r = rsqrtf(s * (1.0f / DV) + 1e-6f);
    float4 z  = *(const float4*)(qkvz + (size_t)t * QKVZ_N + 2 * KEY_DIM + VAL_DIM + h * DV + lane * 4);
    float4 nw = *(const float4*)(norm_w + lane * 4);
    float4 y;
    y.x = x.x * r * nw.x * siluf_(z.x);
    y.y = x.y * r * nw.y * siluf_(z.y);
    y.z = x.z * r * nw.z * siluf_(z.z);
    y.w = x.w * r * nw.w * siluf_(z.w);
    __half h0 = __float2half_rn(y.x), h1 = __float2half_rn(y.y);
    __half h2 = __float2half_rn(y.z), h3 = __float2half_rn(y.w);
    __half l0 = __float2half_rn(y.x - __half2float(h0));
    __half l1 = __float2half_rn(y.y - __half2float(h1));
    __half l2 = __float2half_rn(y.z - __half2float(h2));
    __half l3 = __float2half_rn(y.w - __half2float(h3));
    union { __half2 h2v[2]; uint2 u; } H, L;
    H.h2v[0] = __halves2half2(h0, h1); H.h2v[1] = __halves2half2(h2, h3);
    L.h2v[0] = __halves2half2(l0, l1); L.h2v[1] = __halves2half2(l2, l3);
    int i4 = (t * VAL_DIM + h * DV) / 4 + lane;
    ((uint2*)hi)[i4] = H.u;
    ((uint2*)lo)[i4] = L.u;
}

// ---------------- launch ----------------
extern "C" void kernel_launch(void* const* d_in, const int* in_sizes, int n_in,
                              void* d_out, int out_size)
{
    const float* h_in    = (const float*)d_in[0];
    const float* W_qkvz  = (const float*)d_in[1];
    const float* W_ba    = (const float*)d_in[2];
    const float* conv_w  = (const float*)d_in[3];
    const float* dt_bias = (const float*)d_in[4];
    const float* A_log   = (const float*)d_in[5];
    const float* norm_w  = (const float*)d_in[6];
    const float* W_out   = (const float*)d_in[7];
    float* out = (float*)d_out;

    float *qkvz, *qkv, *ba, *qhat, *khat, *qkdot, *oscan;
    float2* egbeta;
    __half *Wq, *Wo, *A_hi, *A_lo;
    cudaGetSymbolAddress((void**)&qkvz,   g_qkvz);
    cudaGetSymbolAddress((void**)&qkv,    g_qkv);
    cudaGetSymbolAddress((void**)&ba,     g_ba);
    cudaGetSymbolAddress((void**)&egbeta, g_egbeta);
    cudaGetSymbolAddress((void**)&qhat,   g_qhat);
    cudaGetSymbolAddress((void**)&khat,   g_khat);
    cudaGetSymbolAddress((void**)&qkdot,  g_qkdot);
    cudaGetSymbolAddress((void**)&oscan,  g_oscan);
    cudaGetSymbolAddress((void**)&Wq,     g_Wq);
    cudaGetSymbolAddress((void**)&Wo,     g_Wo);
    cudaGetSymbolAddress((void**)&A_hi,   g_A_hi);
    cudaGetSymbolAddress((void**)&A_lo,   g_A_lo);

    cudaFuncSetAttribute(gemm_tc<1>, cudaFuncAttributeMaxDynamicSharedMemorySize, GT_SMEM);
    cudaFuncSetAttribute(gemm_tc<0>, cudaFuncAttributeMaxDynamicSharedMemorySize, GT_SMEM);
    cudaFuncSetAttribute(gdn_scan, cudaFuncAttributeMaxDynamicSharedMemorySize, SC_SMEM);

    // prep
    {
        dim3 blk(32, 8);
        tr_half<<<dim3(QKVZ_N / 32, HID / 32), blk>>>(W_qkvz, Wq, HID, QKVZ_N);
        tr_half<<<dim3(HID / 32, VAL_DIM / 32), blk>>>(W_out, Wo, VAL_DIM, HID);
    }
    cvt_split<<<(T_SEQ * HID / 4 + 255) / 256, 256>>>(h_in, A_hi, A_lo, T_SEQ * HID / 4);

    // GEMM1: qkvz = h @ W_qkvz   [2048 x 12288], K=2048 (split-A, 2 passes)
    gemm_tc<1><<<dim3(T_SEQ / 128, QKVZ_N / 128), 256, GT_SMEM>>>(A_hi, A_lo, Wq, qkvz, QKVZ_N, HID);

    gemm_ba<<<T_SEQ / 64, 256>>>(h_in, W_ba, ba);
    conv_silu<<<((T_SEQ / 4) * CONV_DIM) / 256, 256>>>(qkvz, conv_w, qkv);
    gate_prep<<<(T_SEQ * NUM_V) / 256, 256>>>(ba, A_log, dt_bias, egbeta);
    l2norm_qk_dot<<<(T_SEQ * NUM_K) / 8, 256>>>(qkv, qhat, khat, qkdot);
    gdn_scan<<<NUM_V * 4, 512, SC_SMEM>>>(qhat, khat, qkv, (const float*)egbeta, qkdot, oscan);
    rms_gate_split<<<(T_SEQ * NUM_V) / 8, 256>>>(oscan, qkvz, norm_w, A_hi, A_lo);

    // GEMM2: out = gated @ W_out  [2048 x 2048], K=4096 (single-pass fp16 A)
    gemm_tc<0><<<dim3(T_SEQ / 128, HID / 128), 256, GT_SMEM>>>(A_hi, A_lo, Wo, out, HID, VAL_DIM);
}